// round 1
// baseline (speedup 1.0000x reference)
#include <cuda_runtime.h>

#define Bb   4
#define Ss   2048
#define Dd   512
#define Hh   8
#define DHh  64
#define Mrows (Bb * Ss)   // 8192

// ---------------- scratch (static device globals; no runtime allocation) ---
__device__ float g_qd [Mrows * Dd];
__device__ float g_qt [Mrows * Dd];
__device__ float g_kd [Mrows * Dd];
__device__ float g_kt [Mrows * Dd];
__device__ float g_v  [Mrows * Dd];
__device__ float g_ctx[Mrows * Dd];
__device__ float g_y  [Mrows * Dd];

// ---------------------------------------------------------------------------
// Generic SGEMM: Y[M,512] = X1@W1 + b1 (+ X2@W2 + b2) (+ res)
// 128x128 block tile, K=512, BK=8, 256 threads, 8x8 per thread.
// ---------------------------------------------------------------------------
__global__ __launch_bounds__(256, 2)
void gemm512(const float* __restrict__ X1, const float* __restrict__ W1,
             const float* __restrict__ b1,
             const float* __restrict__ X2, const float* __restrict__ W2,
             const float* __restrict__ b2,
             const float* __restrict__ res, float* __restrict__ Y)
{
    __shared__ float As[8][132];   // A transposed: As[k][m]
    __shared__ float Bs[8][132];   // B natural:    Bs[k][n]

    const int tid = threadIdx.x;
    const int tx  = tid & 15;
    const int ty  = tid >> 4;
    const int m0  = blockIdx.y * 128;
    const int n0  = blockIdx.x * 128;

    float acc[8][8];
#pragma unroll
    for (int i = 0; i < 8; i++)
#pragma unroll
        for (int j = 0; j < 8; j++) acc[i][j] = 0.0f;

    const int ar = tid >> 1;           // 0..127 (A row)
    const int ak = (tid & 1) * 4;      // 0 or 4 (A k-col)
    const int br = tid >> 5;           // 0..7   (B k-row)
    const int bc = (tid & 31) * 4;     // 0..124 (B n-col)

#pragma unroll 1
    for (int pass = 0; pass < 2; ++pass) {
        const float* X = pass ? X2 : X1;
        const float* W = pass ? W2 : W1;
        if (X == nullptr) break;
#pragma unroll 1
        for (int k0 = 0; k0 < Dd; k0 += 8) {
            float4 av = *(const float4*)(X + (size_t)(m0 + ar) * Dd + k0 + ak);
            float4 bv = *(const float4*)(W + (size_t)(k0 + br) * Dd + n0 + bc);
            __syncthreads();   // previous tile fully consumed
            As[ak + 0][ar] = av.x;
            As[ak + 1][ar] = av.y;
            As[ak + 2][ar] = av.z;
            As[ak + 3][ar] = av.w;
            *(float4*)&Bs[br][bc] = bv;
            __syncthreads();
#pragma unroll
            for (int kk = 0; kk < 8; ++kk) {
                float4 a0 = *(const float4*)&As[kk][ty * 8];
                float4 a1 = *(const float4*)&As[kk][ty * 8 + 4];
                float4 c0 = *(const float4*)&Bs[kk][tx * 8];
                float4 c1 = *(const float4*)&Bs[kk][tx * 8 + 4];
                float a[8] = {a0.x, a0.y, a0.z, a0.w, a1.x, a1.y, a1.z, a1.w};
                float c[8] = {c0.x, c0.y, c0.z, c0.w, c1.x, c1.y, c1.z, c1.w};
#pragma unroll
                for (int i = 0; i < 8; i++)
#pragma unroll
                    for (int j = 0; j < 8; j++)
                        acc[i][j] = fmaf(a[i], c[j], acc[i][j]);
            }
        }
    }

    // epilogue: bias (+bias2) (+residual)
    float bias[8];
#pragma unroll
    for (int j = 0; j < 8; j++) bias[j] = b1[n0 + tx * 8 + j];
    if (b2 != nullptr) {
#pragma unroll
        for (int j = 0; j < 8; j++) bias[j] += b2[n0 + tx * 8 + j];
    }

#pragma unroll
    for (int i = 0; i < 8; i++) {
        size_t off = (size_t)(m0 + ty * 8 + i) * Dd + n0 + tx * 8;
        float o[8];
#pragma unroll
        for (int j = 0; j < 8; j++) o[j] = acc[i][j] + bias[j];
        if (res != nullptr) {
            float4 r0 = *(const float4*)(res + off);
            float4 r1 = *(const float4*)(res + off + 4);
            o[0] += r0.x; o[1] += r0.y; o[2] += r0.z; o[3] += r0.w;
            o[4] += r1.x; o[5] += r1.y; o[6] += r1.z; o[7] += r1.w;
        }
        *(float4*)(Y + off)     = make_float4(o[0], o[1], o[2], o[3]);
        *(float4*)(Y + off + 4) = make_float4(o[4], o[5], o[6], o[7]);
    }
}

// ---------------------------------------------------------------------------
// Flash-attention (FA2 style), fp32.
// Per block: one (b,h) pair, 64 query rows. Loops over 2048 keys in 64-key
// tiles. QK head dim = 128 (qd||qt concatenated), V dim = 64 (vd+vt presummed).
// ---------------------------------------------------------------------------
#define PQ 68   // padded row stride in floats (float4-aligned, conflict-light)

__global__ __launch_bounds__(256)
void attn(const float* __restrict__ qd, const float* __restrict__ qt,
          const float* __restrict__ kd, const float* __restrict__ kt,
          const float* __restrict__ v,  float* __restrict__ ctx)
{
    extern __shared__ float sm[];
    float* Qs = sm;                 // [128][PQ]  (transposed: Qs[e][q])
    float* Ks = Qs + 128 * PQ;      // [128][PQ]  (transposed: Ks[e][key])
    float* Vs = Ks + 128 * PQ;      // [64][PQ]   (natural:    Vs[key][e])
    float* Ps = Vs + 64 * PQ;       // [64][PQ]   (natural:    Ps[q][key])

    const int tid = threadIdx.x;
    const int tx  = tid & 15;
    const int ty  = tid >> 4;
    const int bh  = blockIdx.y;
    const int b   = bh >> 3;
    const int h   = bh & 7;
    const int q0  = blockIdx.x * 64;
    const size_t base = (size_t)b * Ss * Dd + (size_t)h * DHh;
    const float scale = 0.125f;     // 1/sqrt(64)

    // load Q tile: 64 q x 128 e, transposed into smem
    for (int idx = tid; idx < 64 * 128; idx += 256) {
        int q = idx >> 7;
        int e = idx & 127;
        float val = (e < 64) ? qd[base + (size_t)(q0 + q) * Dd + e]
                             : qt[base + (size_t)(q0 + q) * Dd + (e - 64)];
        Qs[e * PQ + q] = val;
    }

    float accO[4][4];
    float mrow[4], lrow[4];
#pragma unroll
    for (int i = 0; i < 4; i++) {
        mrow[i] = -1e30f; lrow[i] = 0.0f;
#pragma unroll
        for (int j = 0; j < 4; j++) accO[i][j] = 0.0f;
    }

    for (int k0 = 0; k0 < Ss; k0 += 64) {
        __syncthreads();   // previous tile (Ks/Vs/Ps) fully consumed
        // K tile: 64 keys x 128 e, transposed
        for (int idx = tid; idx < 64 * 128; idx += 256) {
            int key = idx >> 7;
            int e   = idx & 127;
            float val = (e < 64) ? kd[base + (size_t)(k0 + key) * Dd + e]
                                 : kt[base + (size_t)(k0 + key) * Dd + (e - 64)];
            Ks[e * PQ + key] = val;
        }
        // V tile: 64 keys x 64 e, natural
        for (int idx = tid; idx < 64 * 16; idx += 256) {
            int key = idx >> 4;
            int e4  = (idx & 15) * 4;
            *(float4*)&Vs[key * PQ + e4] =
                *(const float4*)&v[base + (size_t)(k0 + key) * Dd + e4];
        }
        __syncthreads();

        // S = Q @ K^T  (64x64, k-dim 128)
        float accS[4][4];
#pragma unroll
        for (int i = 0; i < 4; i++)
#pragma unroll
            for (int j = 0; j < 4; j++) accS[i][j] = 0.0f;

#pragma unroll 8
        for (int kk = 0; kk < 128; ++kk) {
            float4 a = *(const float4*)&Qs[kk * PQ + ty * 4];
            float4 c = *(const float4*)&Ks[kk * PQ + tx * 4];
            float av[4] = {a.x, a.y, a.z, a.w};
            float cv[4] = {c.x, c.y, c.z, c.w};
#pragma unroll
            for (int i = 0; i < 4; i++)
#pragma unroll
                for (int j = 0; j < 4; j++)
                    accS[i][j] = fmaf(av[i], cv[j], accS[i][j]);
        }

        // online softmax over the 64-key tile (row reduce across 16 tx lanes)
#pragma unroll
        for (int i = 0; i < 4; i++) {
            float mx = -1e30f;
#pragma unroll
            for (int j = 0; j < 4; j++) {
                accS[i][j] *= scale;
                mx = fmaxf(mx, accS[i][j]);
            }
#pragma unroll
            for (int off = 1; off < 16; off <<= 1)
                mx = fmaxf(mx, __shfl_xor_sync(0xffffffffu, mx, off));
            float mnew = fmaxf(mrow[i], mx);
            float corr = __expf(mrow[i] - mnew);
            mrow[i] = mnew;
            float ps = 0.0f;
#pragma unroll
            for (int j = 0; j < 4; j++) {
                float p = __expf(accS[i][j] - mnew);
                accS[i][j] = p;
                ps += p;
            }
#pragma unroll
            for (int off = 1; off < 16; off <<= 1)
                ps += __shfl_xor_sync(0xffffffffu, ps, off);
            lrow[i] = lrow[i] * corr + ps;
#pragma unroll
            for (int j = 0; j < 4; j++) accO[i][j] *= corr;
        }

        // stash P into smem (natural layout, float4 rows)
#pragma unroll
        for (int i = 0; i < 4; i++)
            *(float4*)&Ps[(ty * 4 + i) * PQ + tx * 4] =
                make_float4(accS[i][0], accS[i][1], accS[i][2], accS[i][3]);
        __syncthreads();

        // ctx += P @ V  (64x64, k-dim 64)
#pragma unroll 4
        for (int kk = 0; kk < 64; ++kk) {
            float4 c = *(const float4*)&Vs[kk * PQ + tx * 4];
            float cv[4] = {c.x, c.y, c.z, c.w};
#pragma unroll
            for (int i = 0; i < 4; i++) {
                float av = Ps[(ty * 4 + i) * PQ + kk];
#pragma unroll
                for (int j = 0; j < 4; j++)
                    accO[i][j] = fmaf(av, cv[j], accO[i][j]);
            }
        }
    }

    // epilogue: normalize by l, write ctx[b, q, h*64 + e]
#pragma unroll
    for (int i = 0; i < 4; i++) {
        float inv = 1.0f / lrow[i];
        size_t off = base + (size_t)(q0 + ty * 4 + i) * Dd + tx * 4;
        *(float4*)(ctx + off) = make_float4(accO[i][0] * inv, accO[i][1] * inv,
                                            accO[i][2] * inv, accO[i][3] * inv);
    }
}

// ---------------------------------------------------------------------------
// LayerNorm over rows of 512: one block (128 threads) per row.
// ---------------------------------------------------------------------------
__global__ __launch_bounds__(128)
void layernorm(const float* __restrict__ Y, const float* __restrict__ gamma,
               const float* __restrict__ beta, float* __restrict__ out)
{
    __shared__ float rs[4], rss[4];
    const int row = blockIdx.x;
    const int tid = threadIdx.x;
    const size_t off = (size_t)row * Dd + tid * 4;

    float4 val = *(const float4*)(Y + off);
    float s  = val.x + val.y + val.z + val.w;
    float ss = val.x * val.x + val.y * val.y + val.z * val.z + val.w * val.w;
#pragma unroll
    for (int o = 16; o > 0; o >>= 1) {
        s  += __shfl_xor_sync(0xffffffffu, s,  o);
        ss += __shfl_xor_sync(0xffffffffu, ss, o);
    }
    const int wid = tid >> 5;
    if ((tid & 31) == 0) { rs[wid] = s; rss[wid] = ss; }
    __syncthreads();
    s  = rs[0]  + rs[1]  + rs[2]  + rs[3];
    ss = rss[0] + rss[1] + rss[2] + rss[3];

    float mean = s * (1.0f / Dd);
    float var  = ss * (1.0f / Dd) - mean * mean;
    float rstd = rsqrtf(var + 1e-5f);

    float4 g  = *(const float4*)(gamma + tid * 4);
    float4 be = *(const float4*)(beta  + tid * 4);
    float4 o;
    o.x = (val.x - mean) * rstd * g.x + be.x;
    o.y = (val.y - mean) * rstd * g.y + be.y;
    o.z = (val.z - mean) * rstd * g.z + be.z;
    o.w = (val.w - mean) * rstd * g.w + be.w;
    *(float4*)(out + off) = o;
}

// ---------------------------------------------------------------------------
extern "C" void kernel_launch(void* const* d_in, const int* in_sizes, int n_in,
                              void* d_out, int out_size)
{
    const float* Q_data = (const float*)d_in[0];
    const float* Q_time = (const float*)d_in[1];
    const float* K_data = (const float*)d_in[2];
    const float* K_time = (const float*)d_in[3];
    const float* V_data = (const float*)d_in[4];
    const float* V_time = (const float*)d_in[5];
    const float* Wq_d = (const float*)d_in[6];
    const float* bq_d = (const float*)d_in[7];
    const float* Wq_t = (const float*)d_in[8];
    const float* bq_t = (const float*)d_in[9];
    const float* Wk_d = (const float*)d_in[10];
    const float* bk_d = (const float*)d_in[11];
    const float* Wk_t = (const float*)d_in[12];
    const float* bk_t = (const float*)d_in[13];
    const float* Wv_d = (const float*)d_in[14];
    const float* bv_d = (const float*)d_in[15];
    const float* Wv_t = (const float*)d_in[16];
    const float* bv_t = (const float*)d_in[17];
    const float* Wo   = (const float*)d_in[18];
    const float* bo   = (const float*)d_in[19];
    const float* gamma= (const float*)d_in[20];
    const float* beta = (const float*)d_in[21];
    float* out = (float*)d_out;

    float *qd, *qt, *kd, *kt, *vv, *ctx, *y;
    cudaGetSymbolAddress((void**)&qd,  g_qd);
    cudaGetSymbolAddress((void**)&qt,  g_qt);
    cudaGetSymbolAddress((void**)&kd,  g_kd);
    cudaGetSymbolAddress((void**)&kt,  g_kt);
    cudaGetSymbolAddress((void**)&vv,  g_v);
    cudaGetSymbolAddress((void**)&ctx, g_ctx);
    cudaGetSymbolAddress((void**)&y,   g_y);

    dim3 gg(Dd / 128, Mrows / 128);   // (4, 64)

    // projections
    gemm512<<<gg, 256>>>(Q_data, Wq_d, bq_d, nullptr, nullptr, nullptr, nullptr, qd);
    gemm512<<<gg, 256>>>(Q_time, Wq_t, bq_t, nullptr, nullptr, nullptr, nullptr, qt);
    gemm512<<<gg, 256>>>(K_data, Wk_d, bk_d, nullptr, nullptr, nullptr, nullptr, kd);
    gemm512<<<gg, 256>>>(K_time, Wk_t, bk_t, nullptr, nullptr, nullptr, nullptr, kt);
    // V = Vd@Wvd + bvd + Vt@Wvt + bvt   (fused dual-K GEMM)
    gemm512<<<gg, 256>>>(V_data, Wv_d, bv_d, V_time, Wv_t, bv_t, nullptr, vv);

    // attention
    size_t smem = (size_t)(128 * PQ * 2 + 64 * PQ * 2) * sizeof(float); // 104448 B
    cudaFuncSetAttribute(attn, cudaFuncAttributeMaxDynamicSharedMemorySize, (int)smem);
    attn<<<dim3(Ss / 64, Bb * Hh), 256, smem>>>(qd, qt, kd, kt, vv, ctx);

    // output projection + bias + residual, then LayerNorm
    gemm512<<<gg, 256>>>(ctx, Wo, bo, nullptr, nullptr, nullptr, Q_data, y);
    layernorm<<<Mrows, 128>>>(y, gamma, beta, out);
}

// round 2
// speedup vs baseline: 1.0107x; 1.0107x over previous
#include <cuda_runtime.h>

#define Bb   4
#define Ss   2048
#define Dd   512
#define Hh   8
#define DHh  64
#define Mrows (Bb * Ss)   // 8192

// ---------------- scratch (static device globals; no runtime allocation) ---
__device__ float g_qd [Mrows * Dd];
__device__ float g_qt [Mrows * Dd];
__device__ float g_kd [Mrows * Dd];
__device__ float g_kt [Mrows * Dd];
__device__ float g_v  [Mrows * Dd];
__device__ float g_ctx[Mrows * Dd];
__device__ float g_y  [Mrows * Dd];

// ---------------------------------------------------------------------------
// Generic SGEMM: Y[M,512] = X1@W1 + b1 (+ X2@W2 + b2) (+ res)
// 128x128 block tile, K=512, BK=8, 256 threads, 8x8 per thread.
// ---------------------------------------------------------------------------
__global__ __launch_bounds__(256, 2)
void gemm512(const float* __restrict__ X1, const float* __restrict__ W1,
             const float* __restrict__ b1,
             const float* __restrict__ X2, const float* __restrict__ W2,
             const float* __restrict__ b2,
             const float* __restrict__ res, float* __restrict__ Y)
{
    __shared__ float As[8][132];   // A transposed: As[k][m]
    __shared__ float Bs[8][132];   // B natural:    Bs[k][n]

    const int tid = threadIdx.x;
    const int tx  = tid & 15;
    const int ty  = tid >> 4;
    const int m0  = blockIdx.y * 128;
    const int n0  = blockIdx.x * 128;

    float acc[8][8];
#pragma unroll
    for (int i = 0; i < 8; i++)
#pragma unroll
        for (int j = 0; j < 8; j++) acc[i][j] = 0.0f;

    const int ar = tid >> 1;           // 0..127 (A row)
    const int ak = (tid & 1) * 4;      // 0 or 4 (A k-col)
    const int br = tid >> 5;           // 0..7   (B k-row)
    const int bc = (tid & 31) * 4;     // 0..124 (B n-col)

#pragma unroll 1
    for (int pass = 0; pass < 2; ++pass) {
        const float* X = pass ? X2 : X1;
        const float* W = pass ? W2 : W1;
        if (X == nullptr) break;
#pragma unroll 1
        for (int k0 = 0; k0 < Dd; k0 += 8) {
            float4 av = *(const float4*)(X + (size_t)(m0 + ar) * Dd + k0 + ak);
            float4 bv = *(const float4*)(W + (size_t)(k0 + br) * Dd + n0 + bc);
            __syncthreads();   // previous tile fully consumed
            As[ak + 0][ar] = av.x;
            As[ak + 1][ar] = av.y;
            As[ak + 2][ar] = av.z;
            As[ak + 3][ar] = av.w;
            *(float4*)&Bs[br][bc] = bv;
            __syncthreads();
#pragma unroll
            for (int kk = 0; kk < 8; ++kk) {
                float4 a0 = *(const float4*)&As[kk][ty * 8];
                float4 a1 = *(const float4*)&As[kk][ty * 8 + 4];
                float4 c0 = *(const float4*)&Bs[kk][tx * 8];
                float4 c1 = *(const float4*)&Bs[kk][tx * 8 + 4];
                float a[8] = {a0.x, a0.y, a0.z, a0.w, a1.x, a1.y, a1.z, a1.w};
                float c[8] = {c0.x, c0.y, c0.z, c0.w, c1.x, c1.y, c1.z, c1.w};
#pragma unroll
                for (int i = 0; i < 8; i++)
#pragma unroll
                    for (int j = 0; j < 8; j++)
                        acc[i][j] = fmaf(a[i], c[j], acc[i][j]);
            }
        }
    }

    // epilogue: bias (+bias2) (+residual)
    float bias[8];
#pragma unroll
    for (int j = 0; j < 8; j++) bias[j] = b1[n0 + tx * 8 + j];
    if (b2 != nullptr) {
#pragma unroll
        for (int j = 0; j < 8; j++) bias[j] += b2[n0 + tx * 8 + j];
    }

#pragma unroll
    for (int i = 0; i < 8; i++) {
        size_t off = (size_t)(m0 + ty * 8 + i) * Dd + n0 + tx * 8;
        float o[8];
#pragma unroll
        for (int j = 0; j < 8; j++) o[j] = acc[i][j] + bias[j];
        if (res != nullptr) {
            float4 r0 = *(const float4*)(res + off);
            float4 r1 = *(const float4*)(res + off + 4);
            o[0] += r0.x; o[1] += r0.y; o[2] += r0.z; o[3] += r0.w;
            o[4] += r1.x; o[5] += r1.y; o[6] += r1.z; o[7] += r1.w;
        }
        *(float4*)(Y + off)     = make_float4(o[0], o[1], o[2], o[3]);
        *(float4*)(Y + off + 4) = make_float4(o[4], o[5], o[6], o[7]);
    }
}

// ---------------------------------------------------------------------------
// Flash-attention (FA2 style), fp32.
// Per block: one (b,h) pair, 64 query rows. Loops over 2048 keys in 64-key
// tiles. QK head dim = 128 (qd||qt concatenated), V dim = 64 (vd+vt presummed).
// ---------------------------------------------------------------------------
#define PQ 68   // padded row stride in floats (float4-aligned, conflict-light)

__global__ __launch_bounds__(256)
void attn(const float* __restrict__ qd, const float* __restrict__ qt,
          const float* __restrict__ kd, const float* __restrict__ kt,
          const float* __restrict__ v,  float* __restrict__ ctx)
{
    extern __shared__ float sm[];
    float* Qs = sm;                 // [128][PQ]  (transposed: Qs[e][q])
    float* Ks = Qs + 128 * PQ;      // [128][PQ]  (transposed: Ks[e][key])
    float* Vs = Ks + 128 * PQ;      // [64][PQ]   (natural:    Vs[key][e])
    float* Ps = Vs + 64 * PQ;       // [64][PQ]   (natural:    Ps[q][key])

    const int tid = threadIdx.x;
    const int tx  = tid & 15;
    const int ty  = tid >> 4;
    const int bh  = blockIdx.y;
    const int b   = bh >> 3;
    const int h   = bh & 7;
    const int q0  = blockIdx.x * 64;
    const size_t base = (size_t)b * Ss * Dd + (size_t)h * DHh;
    const float scale = 0.125f;     // 1/sqrt(64)

    // load Q tile: 64 q x 128 e, transposed into smem
    for (int idx = tid; idx < 64 * 128; idx += 256) {
        int q = idx >> 7;
        int e = idx & 127;
        float val = (e < 64) ? qd[base + (size_t)(q0 + q) * Dd + e]
                             : qt[base + (size_t)(q0 + q) * Dd + (e - 64)];
        Qs[e * PQ + q] = val;
    }

    float accO[4][4];
    float mrow[4], lrow[4];
#pragma unroll
    for (int i = 0; i < 4; i++) {
        mrow[i] = -1e30f; lrow[i] = 0.0f;
#pragma unroll
        for (int j = 0; j < 4; j++) accO[i][j] = 0.0f;
    }

    for (int k0 = 0; k0 < Ss; k0 += 64) {
        __syncthreads();   // previous tile (Ks/Vs/Ps) fully consumed
        // K tile: 64 keys x 128 e, transposed
        for (int idx = tid; idx < 64 * 128; idx += 256) {
            int key = idx >> 7;
            int e   = idx & 127;
            float val = (e < 64) ? kd[base + (size_t)(k0 + key) * Dd + e]
                                 : kt[base + (size_t)(k0 + key) * Dd + (e - 64)];
            Ks[e * PQ + key] = val;
        }
        // V tile: 64 keys x 64 e, natural
        for (int idx = tid; idx < 64 * 16; idx += 256) {
            int key = idx >> 4;
            int e4  = (idx & 15) * 4;
            *(float4*)&Vs[key * PQ + e4] =
                *(const float4*)&v[base + (size_t)(k0 + key) * Dd + e4];
        }
        __syncthreads();

        // S = Q @ K^T  (64x64, k-dim 128)
        float accS[4][4];
#pragma unroll
        for (int i = 0; i < 4; i++)
#pragma unroll
            for (int j = 0; j < 4; j++) accS[i][j] = 0.0f;

#pragma unroll 8
        for (int kk = 0; kk < 128; ++kk) {
            float4 a = *(const float4*)&Qs[kk * PQ + ty * 4];
            float4 c = *(const float4*)&Ks[kk * PQ + tx * 4];
            float av[4] = {a.x, a.y, a.z, a.w};
            float cv[4] = {c.x, c.y, c.z, c.w};
#pragma unroll
            for (int i = 0; i < 4; i++)
#pragma unroll
                for (int j = 0; j < 4; j++)
                    accS[i][j] = fmaf(av[i], cv[j], accS[i][j]);
        }

        // online softmax over the 64-key tile (row reduce across 16 tx lanes)
#pragma unroll
        for (int i = 0; i < 4; i++) {
            float mx = -1e30f;
#pragma unroll
            for (int j = 0; j < 4; j++) {
                accS[i][j] *= scale;
                mx = fmaxf(mx, accS[i][j]);
            }
#pragma unroll
            for (int off = 1; off < 16; off <<= 1)
                mx = fmaxf(mx, __shfl_xor_sync(0xffffffffu, mx, off));
            float mnew = fmaxf(mrow[i], mx);
            float corr = __expf(mrow[i] - mnew);
            mrow[i] = mnew;
            float ps = 0.0f;
#pragma unroll
            for (int j = 0; j < 4; j++) {
                float p = __expf(accS[i][j] - mnew);
                accS[i][j] = p;
                ps += p;
            }
#pragma unroll
            for (int off = 1; off < 16; off <<= 1)
                ps += __shfl_xor_sync(0xffffffffu, ps, off);
            lrow[i] = lrow[i] * corr + ps;
#pragma unroll
            for (int j = 0; j < 4; j++) accO[i][j] *= corr;
        }

        // stash P into smem (natural layout, float4 rows)
#pragma unroll
        for (int i = 0; i < 4; i++)
            *(float4*)&Ps[(ty * 4 + i) * PQ + tx * 4] =
                make_float4(accS[i][0], accS[i][1], accS[i][2], accS[i][3]);
        __syncthreads();

        // ctx += P @ V  (64x64, k-dim 64)
#pragma unroll 4
        for (int kk = 0; kk < 64; ++kk) {
            float4 c = *(const float4*)&Vs[kk * PQ + tx * 4];
            float cv[4] = {c.x, c.y, c.z, c.w};
#pragma unroll
            for (int i = 0; i < 4; i++) {
                float av = Ps[(ty * 4 + i) * PQ + kk];
#pragma unroll
                for (int j = 0; j < 4; j++)
                    accO[i][j] = fmaf(av, cv[j], accO[i][j]);
            }
        }
    }

    // epilogue: normalize by l, write ctx[b, q, h*64 + e]
#pragma unroll
    for (int i = 0; i < 4; i++) {
        float inv = 1.0f / lrow[i];
        size_t off = base + (size_t)(q0 + ty * 4 + i) * Dd + tx * 4;
        *(float4*)(ctx + off) = make_float4(accO[i][0] * inv, accO[i][1] * inv,
                                            accO[i][2] * inv, accO[i][3] * inv);
    }
}

// ---------------------------------------------------------------------------
// LayerNorm over rows of 512: one block (128 threads) per row.
// ---------------------------------------------------------------------------
__global__ __launch_bounds__(128)
void layernorm(const float* __restrict__ Y, const float* __restrict__ gamma,
               const float* __restrict__ beta, float* __restrict__ out)
{
    __shared__ float rs[4], rss[4];
    const int row = blockIdx.x;
    const int tid = threadIdx.x;
    const size_t off = (size_t)row * Dd + tid * 4;

    float4 val = *(const float4*)(Y + off);
    float s  = val.x + val.y + val.z + val.w;
    float ss = val.x * val.x + val.y * val.y + val.z * val.z + val.w * val.w;
#pragma unroll
    for (int o = 16; o > 0; o >>= 1) {
        s  += __shfl_xor_sync(0xffffffffu, s,  o);
        ss += __shfl_xor_sync(0xffffffffu, ss, o);
    }
    const int wid = tid >> 5;
    if ((tid & 31) == 0) { rs[wid] = s; rss[wid] = ss; }
    __syncthreads();
    s  = rs[0]  + rs[1]  + rs[2]  + rs[3];
    ss = rss[0] + rss[1] + rss[2] + rss[3];

    float mean = s * (1.0f / Dd);
    float var  = ss * (1.0f / Dd) - mean * mean;
    float rstd = rsqrtf(var + 1e-5f);

    float4 g  = *(const float4*)(gamma + tid * 4);
    float4 be = *(const float4*)(beta  + tid * 4);
    float4 o;
    o.x = (val.x - mean) * rstd * g.x + be.x;
    o.y = (val.y - mean) * rstd * g.y + be.y;
    o.z = (val.z - mean) * rstd * g.z + be.z;
    o.w = (val.w - mean) * rstd * g.w + be.w;
    *(float4*)(out + off) = o;
}

// ---------------------------------------------------------------------------
extern "C" void kernel_launch(void* const* d_in, const int* in_sizes, int n_in,
                              void* d_out, int out_size)
{
    const float* Q_data = (const float*)d_in[0];
    const float* Q_time = (const float*)d_in[1];
    const float* K_data = (const float*)d_in[2];
    const float* K_time = (const float*)d_in[3];
    const float* V_data = (const float*)d_in[4];
    const float* V_time = (const float*)d_in[5];
    const float* Wq_d = (const float*)d_in[6];
    const float* bq_d = (const float*)d_in[7];
    const float* Wq_t = (const float*)d_in[8];
    const float* bq_t = (const float*)d_in[9];
    const float* Wk_d = (const float*)d_in[10];
    const float* bk_d = (const float*)d_in[11];
    const float* Wk_t = (const float*)d_in[12];
    const float* bk_t = (const float*)d_in[13];
    const float* Wv_d = (const float*)d_in[14];
    const float* bv_d = (const float*)d_in[15];
    const float* Wv_t = (const float*)d_in[16];
    const float* bv_t = (const float*)d_in[17];
    const float* Wo   = (const float*)d_in[18];
    const float* bo   = (const float*)d_in[19];
    const float* gamma= (const float*)d_in[20];
    const float* beta = (const float*)d_in[21];
    float* out = (float*)d_out;

    float *qd, *qt, *kd, *kt, *vv, *ctx, *y;
    cudaGetSymbolAddress((void**)&qd,  g_qd);
    cudaGetSymbolAddress((void**)&qt,  g_qt);
    cudaGetSymbolAddress((void**)&kd,  g_kd);
    cudaGetSymbolAddress((void**)&kt,  g_kt);
    cudaGetSymbolAddress((void**)&vv,  g_v);
    cudaGetSymbolAddress((void**)&ctx, g_ctx);
    cudaGetSymbolAddress((void**)&y,   g_y);

    dim3 gg(Dd / 128, Mrows / 128);   // (4, 64)

    // projections
    gemm512<<<gg, 256>>>(Q_data, Wq_d, bq_d, nullptr, nullptr, nullptr, nullptr, qd);
    gemm512<<<gg, 256>>>(Q_time, Wq_t, bq_t, nullptr, nullptr, nullptr, nullptr, qt);
    gemm512<<<gg, 256>>>(K_data, Wk_d, bk_d, nullptr, nullptr, nullptr, nullptr, kd);
    gemm512<<<gg, 256>>>(K_time, Wk_t, bk_t, nullptr, nullptr, nullptr, nullptr, kt);
    // V = Vd@Wvd + bvd + Vt@Wvt + bvt   (fused dual-K GEMM)
    gemm512<<<gg, 256>>>(V_data, Wv_d, bv_d, V_time, Wv_t, bv_t, nullptr, vv);

    // attention
    size_t smem = (size_t)(128 * PQ * 2 + 64 * PQ * 2) * sizeof(float); // 104448 B
    cudaFuncSetAttribute(attn, cudaFuncAttributeMaxDynamicSharedMemorySize, (int)smem);
    attn<<<dim3(Ss / 64, Bb * Hh), 256, smem>>>(qd, qt, kd, kt, vv, ctx);

    // output projection + bias + residual, then LayerNorm
    gemm512<<<gg, 256>>>(ctx, Wo, bo, nullptr, nullptr, nullptr, Q_data, y);
    layernorm<<<Mrows, 128>>>(y, gamma, beta, out);
}

// round 3
// speedup vs baseline: 1.0117x; 1.0010x over previous
#include <cuda_runtime.h>

#define Bb   4
#define Ss   2048
#define Dd   512
#define Hh   8
#define DHh  64
#define Mrows (Bb * Ss)   // 8192

// ---------------- scratch (static device globals; no runtime allocation) ---
__device__ float g_qd [Mrows * Dd];
__device__ float g_qt [Mrows * Dd];
__device__ float g_kd [Mrows * Dd];
__device__ float g_kt [Mrows * Dd];
__device__ float g_v  [Mrows * Dd];
__device__ float g_ctx[Mrows * Dd];
__device__ float g_y  [Mrows * Dd];

// ---------------------------------------------------------------------------
// Generic SGEMM: Y[M,512] = X1@W1 + b1 (+ X2@W2 + b2) (+ res)
// 128x128 block tile, K=512, BK=8, 256 threads, 8x8 per thread.
// ---------------------------------------------------------------------------
__global__ __launch_bounds__(256, 2)
void gemm512(const float* __restrict__ X1, const float* __restrict__ W1,
             const float* __restrict__ b1,
             const float* __restrict__ X2, const float* __restrict__ W2,
             const float* __restrict__ b2,
             const float* __restrict__ res, float* __restrict__ Y)
{
    __shared__ float As[8][132];   // A transposed: As[k][m]
    __shared__ float Bs[8][132];   // B natural:    Bs[k][n]

    const int tid = threadIdx.x;
    const int tx  = tid & 15;
    const int ty  = tid >> 4;
    const int m0  = blockIdx.y * 128;
    const int n0  = blockIdx.x * 128;

    float acc[8][8];
#pragma unroll
    for (int i = 0; i < 8; i++)
#pragma unroll
        for (int j = 0; j < 8; j++) acc[i][j] = 0.0f;

    const int ar = tid >> 1;           // 0..127 (A row)
    const int ak = (tid & 1) * 4;      // 0 or 4 (A k-col)
    const int br = tid >> 5;           // 0..7   (B k-row)
    const int bc = (tid & 31) * 4;     // 0..124 (B n-col)

#pragma unroll 1
    for (int pass = 0; pass < 2; ++pass) {
        const float* X = pass ? X2 : X1;
        const float* W = pass ? W2 : W1;
        if (X == nullptr) break;
#pragma unroll 1
        for (int k0 = 0; k0 < Dd; k0 += 8) {
            float4 av = *(const float4*)(X + (size_t)(m0 + ar) * Dd + k0 + ak);
            float4 bv = *(const float4*)(W + (size_t)(k0 + br) * Dd + n0 + bc);
            __syncthreads();   // previous tile fully consumed
            As[ak + 0][ar] = av.x;
            As[ak + 1][ar] = av.y;
            As[ak + 2][ar] = av.z;
            As[ak + 3][ar] = av.w;
            *(float4*)&Bs[br][bc] = bv;
            __syncthreads();
#pragma unroll
            for (int kk = 0; kk < 8; ++kk) {
                float4 a0 = *(const float4*)&As[kk][ty * 8];
                float4 a1 = *(const float4*)&As[kk][ty * 8 + 4];
                float4 c0 = *(const float4*)&Bs[kk][tx * 8];
                float4 c1 = *(const float4*)&Bs[kk][tx * 8 + 4];
                float a[8] = {a0.x, a0.y, a0.z, a0.w, a1.x, a1.y, a1.z, a1.w};
                float c[8] = {c0.x, c0.y, c0.z, c0.w, c1.x, c1.y, c1.z, c1.w};
#pragma unroll
                for (int i = 0; i < 8; i++)
#pragma unroll
                    for (int j = 0; j < 8; j++)
                        acc[i][j] = fmaf(a[i], c[j], acc[i][j]);
            }
        }
    }

    // epilogue: bias (+bias2) (+residual)
    float bias[8];
#pragma unroll
    for (int j = 0; j < 8; j++) bias[j] = b1[n0 + tx * 8 + j];
    if (b2 != nullptr) {
#pragma unroll
        for (int j = 0; j < 8; j++) bias[j] += b2[n0 + tx * 8 + j];
    }

#pragma unroll
    for (int i = 0; i < 8; i++) {
        size_t off = (size_t)(m0 + ty * 8 + i) * Dd + n0 + tx * 8;
        float o[8];
#pragma unroll
        for (int j = 0; j < 8; j++) o[j] = acc[i][j] + bias[j];
        if (res != nullptr) {
            float4 r0 = *(const float4*)(res + off);
            float4 r1 = *(const float4*)(res + off + 4);
            o[0] += r0.x; o[1] += r0.y; o[2] += r0.z; o[3] += r0.w;
            o[4] += r1.x; o[5] += r1.y; o[6] += r1.z; o[7] += r1.w;
        }
        *(float4*)(Y + off)     = make_float4(o[0], o[1], o[2], o[3]);
        *(float4*)(Y + off + 4) = make_float4(o[4], o[5], o[6], o[7]);
    }
}

// ---------------------------------------------------------------------------
// Flash-attention (FA2 style), fp32.
// Per block: one (b,h) pair, 64 query rows. Loops over 2048 keys in 64-key
// tiles. QK head dim = 128 (qd||qt concatenated), V dim = 64 (vd+vt presummed).
// ---------------------------------------------------------------------------
#define PQ 68   // padded row stride in floats (float4-aligned, conflict-light)

__global__ __launch_bounds__(256)
void attn(const float* __restrict__ qd, const float* __restrict__ qt,
          const float* __restrict__ kd, const float* __restrict__ kt,
          const float* __restrict__ v,  float* __restrict__ ctx)
{
    extern __shared__ float sm[];
    float* Qs = sm;                 // [128][PQ]  (transposed: Qs[e][q])
    float* Ks = Qs + 128 * PQ;      // [128][PQ]  (transposed: Ks[e][key])
    float* Vs = Ks + 128 * PQ;      // [64][PQ]   (natural:    Vs[key][e])
    float* Ps = Vs + 64 * PQ;       // [64][PQ]   (natural:    Ps[q][key])

    const int tid = threadIdx.x;
    const int tx  = tid & 15;
    const int ty  = tid >> 4;
    const int bh  = blockIdx.y;
    const int b   = bh >> 3;
    const int h   = bh & 7;
    const int q0  = blockIdx.x * 64;
    const size_t base = (size_t)b * Ss * Dd + (size_t)h * DHh;
    const float scale = 0.125f;     // 1/sqrt(64)

    // load Q tile: 64 q x 128 e, transposed into smem
    for (int idx = tid; idx < 64 * 128; idx += 256) {
        int q = idx >> 7;
        int e = idx & 127;
        float val = (e < 64) ? qd[base + (size_t)(q0 + q) * Dd + e]
                             : qt[base + (size_t)(q0 + q) * Dd + (e - 64)];
        Qs[e * PQ + q] = val;
    }

    float accO[4][4];
    float mrow[4], lrow[4];
#pragma unroll
    for (int i = 0; i < 4; i++) {
        mrow[i] = -1e30f; lrow[i] = 0.0f;
#pragma unroll
        for (int j = 0; j < 4; j++) accO[i][j] = 0.0f;
    }

    for (int k0 = 0; k0 < Ss; k0 += 64) {
        __syncthreads();   // previous tile (Ks/Vs/Ps) fully consumed
        // K tile: 64 keys x 128 e, transposed
        for (int idx = tid; idx < 64 * 128; idx += 256) {
            int key = idx >> 7;
            int e   = idx & 127;
            float val = (e < 64) ? kd[base + (size_t)(k0 + key) * Dd + e]
                                 : kt[base + (size_t)(k0 + key) * Dd + (e - 64)];
            Ks[e * PQ + key] = val;
        }
        // V tile: 64 keys x 64 e, natural
        for (int idx = tid; idx < 64 * 16; idx += 256) {
            int key = idx >> 4;
            int e4  = (idx & 15) * 4;
            *(float4*)&Vs[key * PQ + e4] =
                *(const float4*)&v[base + (size_t)(k0 + key) * Dd + e4];
        }
        __syncthreads();

        // S = Q @ K^T  (64x64, k-dim 128)
        float accS[4][4];
#pragma unroll
        for (int i = 0; i < 4; i++)
#pragma unroll
            for (int j = 0; j < 4; j++) accS[i][j] = 0.0f;

#pragma unroll 8
        for (int kk = 0; kk < 128; ++kk) {
            float4 a = *(const float4*)&Qs[kk * PQ + ty * 4];
            float4 c = *(const float4*)&Ks[kk * PQ + tx * 4];
            float av[4] = {a.x, a.y, a.z, a.w};
            float cv[4] = {c.x, c.y, c.z, c.w};
#pragma unroll
            for (int i = 0; i < 4; i++)
#pragma unroll
                for (int j = 0; j < 4; j++)
                    accS[i][j] = fmaf(av[i], cv[j], accS[i][j]);
        }

        // online softmax over the 64-key tile (row reduce across 16 tx lanes)
#pragma unroll
        for (int i = 0; i < 4; i++) {
            float mx = -1e30f;
#pragma unroll
            for (int j = 0; j < 4; j++) {
                accS[i][j] *= scale;
                mx = fmaxf(mx, accS[i][j]);
            }
#pragma unroll
            for (int off = 1; off < 16; off <<= 1)
                mx = fmaxf(mx, __shfl_xor_sync(0xffffffffu, mx, off));
            float mnew = fmaxf(mrow[i], mx);
            float corr = __expf(mrow[i] - mnew);
            mrow[i] = mnew;
            float ps = 0.0f;
#pragma unroll
            for (int j = 0; j < 4; j++) {
                float p = __expf(accS[i][j] - mnew);
                accS[i][j] = p;
                ps += p;
            }
#pragma unroll
            for (int off = 1; off < 16; off <<= 1)
                ps += __shfl_xor_sync(0xffffffffu, ps, off);
            lrow[i] = lrow[i] * corr + ps;
#pragma unroll
            for (int j = 0; j < 4; j++) accO[i][j] *= corr;
        }

        // stash P into smem (natural layout, float4 rows)
#pragma unroll
        for (int i = 0; i < 4; i++)
            *(float4*)&Ps[(ty * 4 + i) * PQ + tx * 4] =
                make_float4(accS[i][0], accS[i][1], accS[i][2], accS[i][3]);
        __syncthreads();

        // ctx += P @ V  (64x64, k-dim 64)
#pragma unroll 4
        for (int kk = 0; kk < 64; ++kk) {
            float4 c = *(const float4*)&Vs[kk * PQ + tx * 4];
            float cv[4] = {c.x, c.y, c.z, c.w};
#pragma unroll
            for (int i = 0; i < 4; i++) {
                float av = Ps[(ty * 4 + i) * PQ + kk];
#pragma unroll
                for (int j = 0; j < 4; j++)
                    accO[i][j] = fmaf(av, cv[j], accO[i][j]);
            }
        }
    }

    // epilogue: normalize by l, write ctx[b, q, h*64 + e]
#pragma unroll
    for (int i = 0; i < 4; i++) {
        float inv = 1.0f / lrow[i];
        size_t off = base + (size_t)(q0 + ty * 4 + i) * Dd + tx * 4;
        *(float4*)(ctx + off) = make_float4(accO[i][0] * inv, accO[i][1] * inv,
                                            accO[i][2] * inv, accO[i][3] * inv);
    }
}

// ---------------------------------------------------------------------------
// LayerNorm over rows of 512: one block (128 threads) per row.
// ---------------------------------------------------------------------------
__global__ __launch_bounds__(128)
void layernorm(const float* __restrict__ Y, const float* __restrict__ gamma,
               const float* __restrict__ beta, float* __restrict__ out)
{
    __shared__ float rs[4], rss[4];
    const int row = blockIdx.x;
    const int tid = threadIdx.x;
    const size_t off = (size_t)row * Dd + tid * 4;

    float4 val = *(const float4*)(Y + off);
    float s  = val.x + val.y + val.z + val.w;
    float ss = val.x * val.x + val.y * val.y + val.z * val.z + val.w * val.w;
#pragma unroll
    for (int o = 16; o > 0; o >>= 1) {
        s  += __shfl_xor_sync(0xffffffffu, s,  o);
        ss += __shfl_xor_sync(0xffffffffu, ss, o);
    }
    const int wid = tid >> 5;
    if ((tid & 31) == 0) { rs[wid] = s; rss[wid] = ss; }
    __syncthreads();
    s  = rs[0]  + rs[1]  + rs[2]  + rs[3];
    ss = rss[0] + rss[1] + rss[2] + rss[3];

    float mean = s * (1.0f / Dd);
    float var  = ss * (1.0f / Dd) - mean * mean;
    float rstd = rsqrtf(var + 1e-5f);

    float4 g  = *(const float4*)(gamma + tid * 4);
    float4 be = *(const float4*)(beta  + tid * 4);
    float4 o;
    o.x = (val.x - mean) * rstd * g.x + be.x;
    o.y = (val.y - mean) * rstd * g.y + be.y;
    o.z = (val.z - mean) * rstd * g.z + be.z;
    o.w = (val.w - mean) * rstd * g.w + be.w;
    *(float4*)(out + off) = o;
}

// ---------------------------------------------------------------------------
extern "C" void kernel_launch(void* const* d_in, const int* in_sizes, int n_in,
                              void* d_out, int out_size)
{
    const float* Q_data = (const float*)d_in[0];
    const float* Q_time = (const float*)d_in[1];
    const float* K_data = (const float*)d_in[2];
    const float* K_time = (const float*)d_in[3];
    const float* V_data = (const float*)d_in[4];
    const float* V_time = (const float*)d_in[5];
    const float* Wq_d = (const float*)d_in[6];
    const float* bq_d = (const float*)d_in[7];
    const float* Wq_t = (const float*)d_in[8];
    const float* bq_t = (const float*)d_in[9];
    const float* Wk_d = (const float*)d_in[10];
    const float* bk_d = (const float*)d_in[11];
    const float* Wk_t = (const float*)d_in[12];
    const float* bk_t = (const float*)d_in[13];
    const float* Wv_d = (const float*)d_in[14];
    const float* bv_d = (const float*)d_in[15];
    const float* Wv_t = (const float*)d_in[16];
    const float* bv_t = (const float*)d_in[17];
    const float* Wo   = (const float*)d_in[18];
    const float* bo   = (const float*)d_in[19];
    const float* gamma= (const float*)d_in[20];
    const float* beta = (const float*)d_in[21];
    float* out = (float*)d_out;

    float *qd, *qt, *kd, *kt, *vv, *ctx, *y;
    cudaGetSymbolAddress((void**)&qd,  g_qd);
    cudaGetSymbolAddress((void**)&qt,  g_qt);
    cudaGetSymbolAddress((void**)&kd,  g_kd);
    cudaGetSymbolAddress((void**)&kt,  g_kt);
    cudaGetSymbolAddress((void**)&vv,  g_v);
    cudaGetSymbolAddress((void**)&ctx, g_ctx);
    cudaGetSymbolAddress((void**)&y,   g_y);

    dim3 gg(Dd / 128, Mrows / 128);   // (4, 64)

    // projections
    gemm512<<<gg, 256>>>(Q_data, Wq_d, bq_d, nullptr, nullptr, nullptr, nullptr, qd);
    gemm512<<<gg, 256>>>(Q_time, Wq_t, bq_t, nullptr, nullptr, nullptr, nullptr, qt);
    gemm512<<<gg, 256>>>(K_data, Wk_d, bk_d, nullptr, nullptr, nullptr, nullptr, kd);
    gemm512<<<gg, 256>>>(K_time, Wk_t, bk_t, nullptr, nullptr, nullptr, nullptr, kt);
    // V = Vd@Wvd + bvd + Vt@Wvt + bvt   (fused dual-K GEMM)
    gemm512<<<gg, 256>>>(V_data, Wv_d, bv_d, V_time, Wv_t, bv_t, nullptr, vv);

    // attention
    size_t smem = (size_t)(128 * PQ * 2 + 64 * PQ * 2) * sizeof(float); // 104448 B
    cudaFuncSetAttribute(attn, cudaFuncAttributeMaxDynamicSharedMemorySize, (int)smem);
    attn<<<dim3(Ss / 64, Bb * Hh), 256, smem>>>(qd, qt, kd, kt, vv, ctx);

    // output projection + bias + residual, then LayerNorm
    gemm512<<<gg, 256>>>(ctx, Wo, bo, nullptr, nullptr, nullptr, Q_data, y);
    layernorm<<<Mrows, 128>>>(y, gamma, beta, out);
}

// round 6
// speedup vs baseline: 7.4401x; 7.3541x over previous
#include <cuda_runtime.h>
#include <cuda_bf16.h>
typedef unsigned int u32; typedef unsigned long long u64;

__device__ __align__(16) __nv_bfloat16 g_wt[(size_t)7*512*512];
__device__ __align__(16) __nv_bfloat16 g_qdb[(size_t)8192*512];
__device__ __align__(16) __nv_bfloat16 g_qtb[(size_t)8192*512];
__device__ __align__(16) __nv_bfloat16 g_kdb[(size_t)8192*512];
__device__ __align__(16) __nv_bfloat16 g_ktb[(size_t)8192*512];
__device__ __align__(16) __nv_bfloat16 g_vb [(size_t)8192*512];
__device__ __align__(16) __nv_bfloat16 g_ctx[(size_t)8192*512];
__device__ __align__(16) float g_y[(size_t)8192*512];

__device__ __forceinline__ u32 smem_u32(const void* p) {
    u32 a; asm("{ .reg .u64 t; cvta.to.shared.u64 t, %1; cvt.u32.u64 %0, t; }" : "=r"(a) : "l"(p)); return a;
}
__device__ __forceinline__ u32 pack_bf16(float lo, float hi) {
    u32 r; asm("cvt.rn.satfinite.bf16x2.f32 %0, %1, %2;" : "=r"(r) : "f"(hi), "f"(lo)); return r;
}
__device__ __forceinline__ void ldsm4(u32* r, u32 a) {
    asm volatile("ldmatrix.sync.aligned.m8n8.x4.shared.b16 {%0,%1,%2,%3}, [%4];"
        : "=r"(r[0]), "=r"(r[1]), "=r"(r[2]), "=r"(r[3]) : "r"(a));
}
__device__ __forceinline__ void ldsm4t(u32* r, u32 a) {
    asm volatile("ldmatrix.sync.aligned.m8n8.x4.trans.shared.b16 {%0,%1,%2,%3}, [%4];"
        : "=r"(r[0]), "=r"(r[1]), "=r"(r[2]), "=r"(r[3]) : "r"(a));
}
__device__ __forceinline__ void mma16(float* c, const u32* a, u32 b0, u32 b1) {
    asm volatile("mma.sync.aligned.m16n8k16.row.col.f32.bf16.bf16.f32 "
        "{%0,%1,%2,%3}, {%4,%5,%6,%7}, {%8,%9}, {%0,%1,%2,%3};"
        : "+f"(c[0]), "+f"(c[1]), "+f"(c[2]), "+f"(c[3])
        : "r"(a[0]), "r"(a[1]), "r"(a[2]), "r"(a[3]), "r"(b0), "r"(b1));
}

// ---- weight transpose + bf16: Wt[n][k] = W[k][n], 7 matrices ----
__global__ void wtrans(const float* w0, const float* w1, const float* w2, const float* w3,
                       const float* w4, const float* w5, const float* w6, __nv_bfloat16* dst)
{
    __shared__ float t[32][33];
    const float* W;
    switch (blockIdx.z) { case 0: W=w0; break; case 1: W=w1; break; case 2: W=w2; break;
        case 3: W=w3; break; case 4: W=w4; break; case 5: W=w5; break; default: W=w6; }
    int bx = blockIdx.x*32, by = blockIdx.y*32, tx = threadIdx.x, ty = threadIdx.y;
#pragma unroll
    for (int i = 0; i < 4; ++i) t[ty*4+i][tx] = W[(size_t)(by+ty*4+i)*512 + bx+tx];
    __syncthreads();
    __nv_bfloat16* D = dst + (size_t)blockIdx.z*512*512;
#pragma unroll
    for (int i = 0; i < 4; ++i) D[(size_t)(bx+ty*4+i)*512 + by+tx] = __float2bfloat16(t[tx][ty*4+i]);
}

// ---- HMMA GEMM: 128x128 tile, K=512 (x2 if DUAL), 8 warps 2x4 ----
template<bool AFP32, bool DUAL, bool OUTF32>
__global__ __launch_bounds__(256, 2)
void mma_gemm(const void* X0, const __nv_bfloat16* __restrict__ W0,
              const void* X1, const __nv_bfloat16* __restrict__ W1,
              const float* __restrict__ b0p, const float* __restrict__ b1p,
              const float* __restrict__ res, void* Yout)
{
    __shared__ __align__(16) __nv_bfloat16 As[128*72];
    __shared__ __align__(16) __nv_bfloat16 Bs[128*72];
    const int tid = threadIdx.x, l = tid & 31, w = tid >> 5, wr = w >> 2, wc = w & 3;
    const int m0 = blockIdx.y*128, n0 = blockIdx.x*128;
    const u32 sA = smem_u32(As), sB = smem_u32(Bs);

    float acc[4][4][4];
#pragma unroll
    for (int i = 0; i < 4; ++i)
#pragma unroll
        for (int j = 0; j < 4; ++j)
#pragma unroll
            for (int q = 0; q < 4; ++q) acc[i][j][q] = 0.0f;

    const int NCH = DUAL ? 16 : 8;
#pragma unroll 1
    for (int c = 0; c < NCH; ++c) {
        const void* X = (DUAL && c >= 8) ? X1 : X0;
        const __nv_bfloat16* W = (DUAL && c >= 8) ? W1 : W0;
        const int k0 = (c & 7) * 64;
        __syncthreads();
        if (AFP32) {
            const float* Xf = (const float*)X;
#pragma unroll
            for (int i = 0; i < 8; ++i) {
                int v = i*256 + tid, row = v >> 4, c4 = v & 15;
                float4 x = *(const float4*)(Xf + (size_t)(m0+row)*512 + k0 + c4*4);
                *(uint2*)(As + row*72 + c4*4) = make_uint2(pack_bf16(x.x,x.y), pack_bf16(x.z,x.w));
            }
        } else {
            const __nv_bfloat16* Xb = (const __nv_bfloat16*)X;
#pragma unroll
            for (int i = 0; i < 4; ++i) {
                int v = i*256 + tid, row = v >> 3, c8 = v & 7;
                *(uint4*)(As + row*72 + c8*8) = *(const uint4*)(Xb + (size_t)(m0+row)*512 + k0 + c8*8);
            }
        }
#pragma unroll
        for (int i = 0; i < 4; ++i) {
            int v = i*256 + tid, row = v >> 3, c8 = v & 7;
            *(uint4*)(Bs + row*72 + c8*8) = *(const uint4*)(W + (size_t)(n0+row)*512 + k0 + c8*8);
        }
        __syncthreads();
#pragma unroll
        for (int ks = 0; ks < 4; ++ks) {
            u32 af[4][4];
#pragma unroll
            for (int mi = 0; mi < 4; ++mi)
                ldsm4(af[mi], sA + ((wr*64 + mi*16 + (l & 15))*72 + ks*16 + (l >> 4)*8)*2);
#pragma unroll
            for (int ni = 0; ni < 2; ++ni) {
                u32 bf[4];
                ldsm4(bf, sB + ((wc*32 + ni*16 + (l & 15))*72 + ks*16 + (l >> 4)*8)*2);
#pragma unroll
                for (int mi = 0; mi < 4; ++mi) {
                    mma16(acc[mi][ni*2],   af[mi], bf[0], bf[2]);
                    mma16(acc[mi][ni*2+1], af[mi], bf[1], bf[3]);
                }
            }
        }
    }
    // epilogue
#pragma unroll
    for (int mi = 0; mi < 4; ++mi)
#pragma unroll
        for (int nj = 0; nj < 4; ++nj) {
            int gr = m0 + wr*64 + mi*16 + (l >> 2);
            int gc = n0 + wc*32 + nj*8 + (l & 3)*2;
            float2 bv = *(const float2*)(b0p + gc);
            if (DUAL) { float2 b2 = *(const float2*)(b1p + gc); bv.x += b2.x; bv.y += b2.y; }
            float* cc = acc[mi][nj];
            if (OUTF32) {
                float* Y = (float*)Yout;
                float2 r0 = *(const float2*)(res + (size_t)gr*512 + gc);
                float2 r1 = *(const float2*)(res + (size_t)(gr+8)*512 + gc);
                *(float2*)(Y + (size_t)gr*512 + gc)     = make_float2(cc[0]+bv.x+r0.x, cc[1]+bv.y+r0.y);
                *(float2*)(Y + (size_t)(gr+8)*512 + gc) = make_float2(cc[2]+bv.x+r1.x, cc[3]+bv.y+r1.y);
            } else {
                __nv_bfloat16* Y = (__nv_bfloat16*)Yout;
                *(u32*)(Y + (size_t)gr*512 + gc)     = pack_bf16(cc[0]+bv.x, cc[1]+bv.y);
                *(u32*)(Y + (size_t)(gr+8)*512 + gc) = pack_bf16(cc[2]+bv.x, cc[3]+bv.y);
            }
        }
}

// ---- HMMA flash attention: 128q x (b,h) per CTA, 16 key tiles of 128 ----
// smem: Q [128][136] @0, K [128][136] @34816, V [128][72] @69632 (bytes: 88064)
#define ATT_SMEM 88064
__global__ __launch_bounds__(256, 2)
void mma_attn(const __nv_bfloat16* __restrict__ qd, const __nv_bfloat16* __restrict__ qt,
              const __nv_bfloat16* __restrict__ kd, const __nv_bfloat16* __restrict__ kt,
              const __nv_bfloat16* __restrict__ vb, __nv_bfloat16* __restrict__ ctx)
{
    extern __shared__ __align__(16) char sm[];
    const u32 sQ = smem_u32(sm), sK = sQ + 34816, sV = sQ + 69632;
    const int tid = threadIdx.x, l = tid & 31, w = tid >> 5;
    const int q0 = blockIdx.x*128, bh = blockIdx.y, b = bh >> 3, h = bh & 7;
    const size_t rbase = (size_t)b*2048*512 + h*64;

    // Q tile [128 q][128 e] = qd||qt
#pragma unroll
    for (int i = 0; i < 8; ++i) {
        int v = i*256 + tid, row = v >> 4, c16 = v & 15;
        const __nv_bfloat16* src = (c16 < 8) ? qd : qt;
        uint4 x = *(const uint4*)(src + rbase + (size_t)(q0+row)*512 + (c16 & 7)*8);
        *(uint4*)(sm + (row*136 + c16*8)*2) = x;
    }
    float octx[8][4];
#pragma unroll
    for (int i = 0; i < 8; ++i)
#pragma unroll
        for (int q = 0; q < 4; ++q) octx[i][q] = 0.0f;
    float lsum0 = 0.0f, lsum1 = 0.0f;

#pragma unroll 1
    for (int kti = 0; kti < 16; ++kti) {
        const int k0 = kti*128;
        __syncthreads();   // prior iteration's ldmatrix reads done
#pragma unroll
        for (int i = 0; i < 8; ++i) {
            int v = i*256 + tid, row = v >> 4, c16 = v & 15;
            const __nv_bfloat16* src = (c16 < 8) ? kd : kt;
            uint4 x = *(const uint4*)(src + rbase + (size_t)(k0+row)*512 + (c16 & 7)*8);
            *(uint4*)(sm + 34816 + (row*136 + c16*8)*2) = x;
        }
#pragma unroll
        for (int i = 0; i < 4; ++i) {
            int v = i*256 + tid, row = v >> 3, c8 = v & 7;
            uint4 x = *(const uint4*)(vb + rbase + (size_t)(k0+row)*512 + c8*8);
            *(uint4*)(sm + 69632 + (row*72 + c8*8)*2) = x;
        }
        __syncthreads();

        // S = Q @ K^T : warp w -> 16 q rows x 128 keys
        float c[16][4];
#pragma unroll
        for (int i = 0; i < 16; ++i)
#pragma unroll
            for (int q = 0; q < 4; ++q) c[i][q] = 0.0f;
#pragma unroll
        for (int ks = 0; ks < 8; ++ks) {
            u32 af[4];
            ldsm4(af, sQ + ((w*16 + (l & 15))*136 + ks*16 + (l >> 4)*8)*2);
#pragma unroll
            for (int ni = 0; ni < 8; ++ni) {
                u32 bf[4];
                ldsm4(bf, sK + ((ni*16 + (l & 15))*136 + ks*16 + (l >> 4)*8)*2);
                mma16(c[2*ni],   af, bf[0], bf[2]);
                mma16(c[2*ni+1], af, bf[1], bf[3]);
            }
        }
        // softmax (no max-sub) fused with PV; P repacked C-frag -> A-frag
#pragma unroll
        for (int ks = 0; ks < 8; ++ks) {
            float p0 = __expf(c[2*ks][0]*0.125f),   p1 = __expf(c[2*ks][1]*0.125f);
            float p2 = __expf(c[2*ks][2]*0.125f),   p3 = __expf(c[2*ks][3]*0.125f);
            float p4 = __expf(c[2*ks+1][0]*0.125f), p5 = __expf(c[2*ks+1][1]*0.125f);
            float p6 = __expf(c[2*ks+1][2]*0.125f), p7 = __expf(c[2*ks+1][3]*0.125f);
            lsum0 += p0 + p1 + p4 + p5;
            lsum1 += p2 + p3 + p6 + p7;
            u32 pa[4] = {pack_bf16(p0,p1), pack_bf16(p2,p3), pack_bf16(p4,p5), pack_bf16(p6,p7)};
#pragma unroll
            for (int nj4 = 0; nj4 < 4; ++nj4) {
                u32 bf[4];
                ldsm4t(bf, sV + ((ks*16 + (l & 15))*72 + nj4*16 + (l >> 4)*8)*2);
                mma16(octx[2*nj4],   pa, bf[0], bf[1]);
                mma16(octx[2*nj4+1], pa, bf[2], bf[3]);
            }
        }
    }
    // row sums across quad lanes (same row group = same l>>2)
    lsum0 += __shfl_xor_sync(0xffffffffu, lsum0, 1);
    lsum0 += __shfl_xor_sync(0xffffffffu, lsum0, 2);
    lsum1 += __shfl_xor_sync(0xffffffffu, lsum1, 1);
    lsum1 += __shfl_xor_sync(0xffffffffu, lsum1, 2);
    float inv0 = 1.0f / lsum0, inv1 = 1.0f / lsum1;

    size_t gr = (size_t)(b*2048 + q0 + w*16 + (l >> 2));
#pragma unroll
    for (int nj = 0; nj < 8; ++nj) {
        int gc = h*64 + nj*8 + (l & 3)*2;
        *(u32*)(ctx + gr*512 + gc)       = pack_bf16(octx[nj][0]*inv0, octx[nj][1]*inv0);
        *(u32*)(ctx + (gr+8)*512 + gc)   = pack_bf16(octx[nj][2]*inv1, octx[nj][3]*inv1);
    }
}

// ---- LayerNorm rows of 512 ----
__global__ __launch_bounds__(128)
void layernorm(const float* __restrict__ Y, const float* __restrict__ gamma,
               const float* __restrict__ beta, float* __restrict__ out)
{
    __shared__ float rs[4], rss[4];
    const int row = blockIdx.x, tid = threadIdx.x;
    const size_t off = (size_t)row*512 + tid*4;
    float4 val = *(const float4*)(Y + off);
    float s = val.x + val.y + val.z + val.w;
    float ss = val.x*val.x + val.y*val.y + val.z*val.z + val.w*val.w;
#pragma unroll
    for (int o = 16; o > 0; o >>= 1) { s += __shfl_xor_sync(0xffffffffu, s, o); ss += __shfl_xor_sync(0xffffffffu, ss, o); }
    int wid = tid >> 5;
    if ((tid & 31) == 0) { rs[wid] = s; rss[wid] = ss; }
    __syncthreads();
    s = rs[0]+rs[1]+rs[2]+rs[3]; ss = rss[0]+rss[1]+rss[2]+rss[3];
    float mean = s*(1.0f/512), var = ss*(1.0f/512) - mean*mean, rstd = rsqrtf(var + 1e-5f);
    float4 g = *(const float4*)(gamma + tid*4), be = *(const float4*)(beta + tid*4), o;
    o.x = (val.x-mean)*rstd*g.x + be.x; o.y = (val.y-mean)*rstd*g.y + be.y;
    o.z = (val.z-mean)*rstd*g.z + be.z; o.w = (val.w-mean)*rstd*g.w + be.w;
    *(float4*)(out + off) = o;
}

extern "C" void kernel_launch(void* const* d_in, const int* in_sizes, int n_in,
                              void* d_out, int out_size)
{
    const float* Qd = (const float*)d_in[0];  const float* Qt = (const float*)d_in[1];
    const float* Kd = (const float*)d_in[2];  const float* Kt = (const float*)d_in[3];
    const float* Vd = (const float*)d_in[4];  const float* Vt = (const float*)d_in[5];
    const float* Wqd = (const float*)d_in[6];  const float* bqd = (const float*)d_in[7];
    const float* Wqt = (const float*)d_in[8];  const float* bqt = (const float*)d_in[9];
    const float* Wkd = (const float*)d_in[10]; const float* bkd = (const float*)d_in[11];
    const float* Wkt = (const float*)d_in[12]; const float* bkt = (const float*)d_in[13];
    const float* Wvd = (const float*)d_in[14]; const float* bvd = (const float*)d_in[15];
    const float* Wvt = (const float*)d_in[16]; const float* bvt = (const float*)d_in[17];
    const float* Wo  = (const float*)d_in[18]; const float* bo  = (const float*)d_in[19];
    const float* gamma = (const float*)d_in[20]; const float* beta = (const float*)d_in[21];
    float* out = (float*)d_out;

    __nv_bfloat16 *wt, *qdb, *qtb, *kdb, *ktb, *vbp, *ctxb; float* y;
    cudaGetSymbolAddress((void**)&wt,  g_wt);
    cudaGetSymbolAddress((void**)&qdb, g_qdb);
    cudaGetSymbolAddress((void**)&qtb, g_qtb);
    cudaGetSymbolAddress((void**)&kdb, g_kdb);
    cudaGetSymbolAddress((void**)&ktb, g_ktb);
    cudaGetSymbolAddress((void**)&vbp, g_vb);
    cudaGetSymbolAddress((void**)&ctxb, g_ctx);
    cudaGetSymbolAddress((void**)&y,   g_y);

    cudaFuncSetAttribute(mma_attn, cudaFuncAttributeMaxDynamicSharedMemorySize, ATT_SMEM);

    wtrans<<<dim3(16,16,7), dim3(32,8)>>>(Wqd, Wqt, Wkd, Wkt, Wvd, Wvt, Wo, wt);

    dim3 gg(4, 64);
    size_t W = (size_t)512*512;
    mma_gemm<true,false,false><<<gg,256>>>(Qd, wt+0*W, nullptr, nullptr, bqd, nullptr, nullptr, qdb);
    mma_gemm<true,false,false><<<gg,256>>>(Qt, wt+1*W, nullptr, nullptr, bqt, nullptr, nullptr, qtb);
    mma_gemm<true,false,false><<<gg,256>>>(Kd, wt+2*W, nullptr, nullptr, bkd, nullptr, nullptr, kdb);
    mma_gemm<true,false,false><<<gg,256>>>(Kt, wt+3*W, nullptr, nullptr, bkt, nullptr, nullptr, ktb);
    mma_gemm<true,true,false><<<gg,256>>>(Vd, wt+4*W, Vt, wt+5*W, bvd, bvt, nullptr, vbp);

    mma_attn<<<dim3(16,32),256,ATT_SMEM>>>(qdb, qtb, kdb, ktb, vbp, ctxb);

    mma_gemm<false,false,true><<<gg,256>>>(ctxb, wt+6*W, nullptr, nullptr, bo, nullptr, Qd, y);
    layernorm<<<8192,128>>>(y, gamma, beta, out);
}

// round 7
// speedup vs baseline: 7.9142x; 1.0637x over previous
#include <cuda_runtime.h>
#include <cuda_bf16.h>
typedef unsigned int u32; typedef unsigned long long u64;

__device__ __align__(16) __nv_bfloat16 g_wt[(size_t)7*512*512];
__device__ __align__(16) __nv_bfloat16 g_qdb[(size_t)8192*512];
__device__ __align__(16) __nv_bfloat16 g_qtb[(size_t)8192*512];
__device__ __align__(16) __nv_bfloat16 g_kdb[(size_t)8192*512];
__device__ __align__(16) __nv_bfloat16 g_ktb[(size_t)8192*512];
__device__ __align__(16) __nv_bfloat16 g_vb [(size_t)8192*512];
__device__ __align__(16) __nv_bfloat16 g_ctx[(size_t)8192*512];
__device__ __align__(16) float g_y[(size_t)8192*512];

__device__ __forceinline__ u32 smem_u32(const void* p) {
    u32 a; asm("{ .reg .u64 t; cvta.to.shared.u64 t, %1; cvt.u32.u64 %0, t; }" : "=r"(a) : "l"(p)); return a;
}
__device__ __forceinline__ u32 pack_bf16(float lo, float hi) {
    u32 r; asm("cvt.rn.satfinite.bf16x2.f32 %0, %1, %2;" : "=r"(r) : "f"(hi), "f"(lo)); return r;
}
__device__ __forceinline__ void ldsm4(u32* r, u32 a) {
    asm volatile("ldmatrix.sync.aligned.m8n8.x4.shared.b16 {%0,%1,%2,%3}, [%4];"
        : "=r"(r[0]), "=r"(r[1]), "=r"(r[2]), "=r"(r[3]) : "r"(a));
}
__device__ __forceinline__ void ldsm4t(u32* r, u32 a) {
    asm volatile("ldmatrix.sync.aligned.m8n8.x4.trans.shared.b16 {%0,%1,%2,%3}, [%4];"
        : "=r"(r[0]), "=r"(r[1]), "=r"(r[2]), "=r"(r[3]) : "r"(a));
}
__device__ __forceinline__ void mma16(float* c, const u32* a, u32 b0, u32 b1) {
    asm volatile("mma.sync.aligned.m16n8k16.row.col.f32.bf16.bf16.f32 "
        "{%0,%1,%2,%3}, {%4,%5,%6,%7}, {%8,%9}, {%0,%1,%2,%3};"
        : "+f"(c[0]), "+f"(c[1]), "+f"(c[2]), "+f"(c[3])
        : "r"(a[0]), "r"(a[1]), "r"(a[2]), "r"(a[3]), "r"(b0), "r"(b1));
}
__device__ __forceinline__ void cpa16(u32 dst, const void* src) {
    asm volatile("cp.async.cg.shared.global [%0], [%1], 16;" :: "r"(dst), "l"(src));
}
#define CP_COMMIT() asm volatile("cp.async.commit_group;" ::: "memory")
#define CP_WAIT(n)  asm volatile("cp.async.wait_group %0;" :: "n"(n) : "memory")

// ---- weight transpose + bf16: Wt[n][k] = W[k][n], 7 matrices ----
__global__ void wtrans(const float* w0, const float* w1, const float* w2, const float* w3,
                       const float* w4, const float* w5, const float* w6, __nv_bfloat16* dst)
{
    __shared__ float t[32][33];
    const float* W;
    switch (blockIdx.z) { case 0: W=w0; break; case 1: W=w1; break; case 2: W=w2; break;
        case 3: W=w3; break; case 4: W=w4; break; case 5: W=w5; break; default: W=w6; }
    int bx = blockIdx.x*32, by = blockIdx.y*32, tx = threadIdx.x, ty = threadIdx.y;
#pragma unroll
    for (int i = 0; i < 4; ++i) t[ty*4+i][tx] = W[(size_t)(by+ty*4+i)*512 + bx+tx];
    __syncthreads();
    __nv_bfloat16* D = dst + (size_t)blockIdx.z*512*512;
#pragma unroll
    for (int i = 0; i < 4; ++i) D[(size_t)(bx+ty*4+i)*512 + by+tx] = __float2bfloat16(t[tx][ty*4+i]);
}

struct GArgs {
    const void* X0[4]; const __nv_bfloat16* W0[4];
    const float* b0[4]; void* Y[4];
    const void* X1; const __nv_bfloat16* W1; const float* b1;
    const float* res;
};

// ---- HMMA GEMM, register-prefetch pipelined. 128x128 tile, 8 warps 2x4 ----
template<bool AFP32, bool DUAL, bool OUTF32>
__global__ __launch_bounds__(256, 2)
void mma_gemm(GArgs a)
{
    __shared__ __align__(16) __nv_bfloat16 As[128*72];
    __shared__ __align__(16) __nv_bfloat16 Bs[128*72];
    const int tid = threadIdx.x, l = tid & 31, w = tid >> 5, wr = w >> 2, wc = w & 3;
    const int m0 = blockIdx.y*128, n0 = blockIdx.x*128, z = blockIdx.z;
    const u32 sA = smem_u32(As), sB = smem_u32(Bs);
    const void* X0 = a.X0[z]; const __nv_bfloat16* W0 = a.W0[z];
    const float* b0p = a.b0[z]; void* Yout = a.Y[z];

    float acc[4][4][4];
#pragma unroll
    for (int i = 0; i < 4; ++i)
#pragma unroll
        for (int j = 0; j < 4; ++j)
#pragma unroll
            for (int q = 0; q < 4; ++q) acc[i][j][q] = 0.0f;

    const int NCH = DUAL ? 16 : 8;
    uint2 aR[8]; uint4 bR[4];

    auto loadc = [&](int c) {
        const void* X = (DUAL && c >= 8) ? a.X1 : X0;
        const __nv_bfloat16* W = (DUAL && c >= 8) ? a.W1 : W0;
        const int k0 = (c & 7) * 64;
        if (AFP32) {
            const float* Xf = (const float*)X;
#pragma unroll
            for (int i = 0; i < 8; ++i) {
                int v = i*256 + tid, row = v >> 4, c4 = v & 15;
                float4 x = *(const float4*)(Xf + (size_t)(m0+row)*512 + k0 + c4*4);
                aR[i] = make_uint2(pack_bf16(x.x,x.y), pack_bf16(x.z,x.w));
            }
        } else {
            const __nv_bfloat16* Xb = (const __nv_bfloat16*)X;
#pragma unroll
            for (int i = 0; i < 4; ++i) {
                int v = i*256 + tid, row = v >> 3, c8 = v & 7;
                uint4 x = *(const uint4*)(Xb + (size_t)(m0+row)*512 + k0 + c8*8);
                aR[2*i]   = make_uint2(x.x, x.y);
                aR[2*i+1] = make_uint2(x.z, x.w);
            }
        }
#pragma unroll
        for (int i = 0; i < 4; ++i) {
            int v = i*256 + tid, row = v >> 3, c8 = v & 7;
            bR[i] = *(const uint4*)(W + (size_t)(n0+row)*512 + k0 + c8*8);
        }
    };

    loadc(0);
#pragma unroll 1
    for (int c = 0; c < NCH; ++c) {
        __syncthreads();   // prior MMA reads done
        if (AFP32) {
#pragma unroll
            for (int i = 0; i < 8; ++i) {
                int v = i*256 + tid, row = v >> 4, c4 = v & 15;
                *(uint2*)(As + row*72 + c4*4) = aR[i];
            }
        } else {
#pragma unroll
            for (int i = 0; i < 4; ++i) {
                int v = i*256 + tid, row = v >> 3, c8 = v & 7;
                *(uint4*)(As + row*72 + c8*8) = make_uint4(aR[2*i].x, aR[2*i].y, aR[2*i+1].x, aR[2*i+1].y);
            }
        }
#pragma unroll
        for (int i = 0; i < 4; ++i) {
            int v = i*256 + tid, row = v >> 3, c8 = v & 7;
            *(uint4*)(Bs + row*72 + c8*8) = bR[i];
        }
        __syncthreads();
        if (c + 1 < NCH) loadc(c + 1);   // LDG in flight during MMA
#pragma unroll
        for (int ks = 0; ks < 4; ++ks) {
            u32 af[4][4];
#pragma unroll
            for (int mi = 0; mi < 4; ++mi)
                ldsm4(af[mi], sA + ((wr*64 + mi*16 + (l & 15))*72 + ks*16 + (l >> 4)*8)*2);
#pragma unroll
            for (int ni = 0; ni < 2; ++ni) {
                u32 bf[4];
                ldsm4(bf, sB + ((wc*32 + ni*16 + (l & 15))*72 + ks*16 + (l >> 4)*8)*2);
#pragma unroll
                for (int mi = 0; mi < 4; ++mi) {
                    mma16(acc[mi][ni*2],   af[mi], bf[0], bf[2]);
                    mma16(acc[mi][ni*2+1], af[mi], bf[1], bf[3]);
                }
            }
        }
    }
    // epilogue
#pragma unroll
    for (int mi = 0; mi < 4; ++mi)
#pragma unroll
        for (int nj = 0; nj < 4; ++nj) {
            int gr = m0 + wr*64 + mi*16 + (l >> 2);
            int gc = n0 + wc*32 + nj*8 + (l & 3)*2;
            float2 bv = *(const float2*)(b0p + gc);
            if (DUAL) { float2 b2 = *(const float2*)(a.b1 + gc); bv.x += b2.x; bv.y += b2.y; }
            float* cc = acc[mi][nj];
            if (OUTF32) {
                float* Y = (float*)Yout;
                float2 r0 = *(const float2*)(a.res + (size_t)gr*512 + gc);
                float2 r1 = *(const float2*)(a.res + (size_t)(gr+8)*512 + gc);
                *(float2*)(Y + (size_t)gr*512 + gc)     = make_float2(cc[0]+bv.x+r0.x, cc[1]+bv.y+r0.y);
                *(float2*)(Y + (size_t)(gr+8)*512 + gc) = make_float2(cc[2]+bv.x+r1.x, cc[3]+bv.y+r1.y);
            } else {
                __nv_bfloat16* Y = (__nv_bfloat16*)Yout;
                *(u32*)(Y + (size_t)gr*512 + gc)     = pack_bf16(cc[0]+bv.x, cc[1]+bv.y);
                *(u32*)(Y + (size_t)(gr+8)*512 + gc) = pack_bf16(cc[2]+bv.x, cc[3]+bv.y);
            }
        }
}

// ---- HMMA flash attention, cp.async double-buffered K/V, Q frags in regs ----
// smem: K0 @0 [128][136], K1 @34816, V0 @69632 [128][72], V1 @88064 ; total 106496
#define ATT_SMEM 106496
__global__ __launch_bounds__(256, 2)
void mma_attn(const __nv_bfloat16* __restrict__ qd, const __nv_bfloat16* __restrict__ qt,
              const __nv_bfloat16* __restrict__ kd, const __nv_bfloat16* __restrict__ kt,
              const __nv_bfloat16* __restrict__ vb, __nv_bfloat16* __restrict__ ctx)
{
    extern __shared__ __align__(16) char sm[];
    const u32 smb = smem_u32(sm);
    const int tid = threadIdx.x, l = tid & 31, w = tid >> 5;
    const int q0 = blockIdx.x*128, bh = blockIdx.y, b = bh >> 3, h = bh & 7;
    const size_t rbase = (size_t)b*2048*512 + h*64;

    // prologue: Q tile [128][128]=qd||qt into K-buf0, then frags to regs
#pragma unroll
    for (int i = 0; i < 8; ++i) {
        int v = i*256 + tid, row = v >> 4, c16 = v & 15;
        const __nv_bfloat16* src = (c16 < 8) ? qd : qt;
        uint4 x = *(const uint4*)(src + rbase + (size_t)(q0+row)*512 + (c16 & 7)*8);
        *(uint4*)(sm + (row*136 + c16*8)*2) = x;
    }
    __syncthreads();
    u32 qf[8][4];
#pragma unroll
    for (int ks = 0; ks < 8; ++ks)
        ldsm4(qf[ks], smb + ((w*16 + (l & 15))*136 + ks*16 + (l >> 4)*8)*2);
    __syncthreads();

    auto issue = [&](int kti, int buf) {
        const int k0 = kti*128;
        const u32 dK = smb + buf*34816, dV = smb + 69632 + buf*18432;
#pragma unroll
        for (int i = 0; i < 8; ++i) {
            int v = i*256 + tid, row = v >> 4, c16 = v & 15;
            const __nv_bfloat16* src = (c16 < 8) ? kd : kt;
            cpa16(dK + (row*136 + c16*8)*2, src + rbase + (size_t)(k0+row)*512 + (c16 & 7)*8);
        }
#pragma unroll
        for (int i = 0; i < 4; ++i) {
            int v = i*256 + tid, row = v >> 3, c8 = v & 7;
            cpa16(dV + (row*72 + c8*8)*2, vb + rbase + (size_t)(k0+row)*512 + c8*8);
        }
    };

    float octx[8][4];
#pragma unroll
    for (int i = 0; i < 8; ++i)
#pragma unroll
        for (int q = 0; q < 4; ++q) octx[i][q] = 0.0f;
    float lsum0 = 0.0f, lsum1 = 0.0f;

    issue(0, 0); CP_COMMIT();
#pragma unroll 1
    for (int kti = 0; kti < 16; ++kti) {
        if (kti < 15) { issue(kti+1, (kti+1)&1); CP_COMMIT(); CP_WAIT(1); }
        else CP_WAIT(0);
        __syncthreads();
        const u32 sK = smb + (kti&1)*34816, sV = smb + 69632 + (kti&1)*18432;

#pragma unroll
        for (int hf = 0; hf < 2; ++hf) {
            // S half: 16 q-rows x 64 keys
            float c[8][4];
#pragma unroll
            for (int i = 0; i < 8; ++i)
#pragma unroll
                for (int q = 0; q < 4; ++q) c[i][q] = 0.0f;
#pragma unroll
            for (int ks = 0; ks < 8; ++ks) {
#pragma unroll
                for (int kk = 0; kk < 4; ++kk) {
                    u32 bf[4];
                    ldsm4(bf, sK + ((hf*64 + kk*16 + (l & 15))*136 + ks*16 + (l >> 4)*8)*2);
                    mma16(c[2*kk],   qf[ks], bf[0], bf[2]);
                    mma16(c[2*kk+1], qf[ks], bf[1], bf[3]);
                }
            }
            // softmax (no max-sub) + PV for this 64-key half
#pragma unroll
            for (int kk = 0; kk < 4; ++kk) {
                float p0 = __expf(c[2*kk][0]*0.125f),   p1 = __expf(c[2*kk][1]*0.125f);
                float p2 = __expf(c[2*kk][2]*0.125f),   p3 = __expf(c[2*kk][3]*0.125f);
                float p4 = __expf(c[2*kk+1][0]*0.125f), p5 = __expf(c[2*kk+1][1]*0.125f);
                float p6 = __expf(c[2*kk+1][2]*0.125f), p7 = __expf(c[2*kk+1][3]*0.125f);
                lsum0 += p0 + p1 + p4 + p5;
                lsum1 += p2 + p3 + p6 + p7;
                u32 pa[4] = {pack_bf16(p0,p1), pack_bf16(p2,p3), pack_bf16(p4,p5), pack_bf16(p6,p7)};
#pragma unroll
                for (int nj4 = 0; nj4 < 4; ++nj4) {
                    u32 bf[4];
                    ldsm4t(bf, sV + ((hf*64 + kk*16 + (l & 15))*72 + nj4*16 + (l >> 4)*8)*2);
                    mma16(octx[2*nj4],   pa, bf[0], bf[1]);
                    mma16(octx[2*nj4+1], pa, bf[2], bf[3]);
                }
            }
        }
        __syncthreads();   // done reading this buffer
    }
    lsum0 += __shfl_xor_sync(0xffffffffu, lsum0, 1);
    lsum0 += __shfl_xor_sync(0xffffffffu, lsum0, 2);
    lsum1 += __shfl_xor_sync(0xffffffffu, lsum1, 1);
    lsum1 += __shfl_xor_sync(0xffffffffu, lsum1, 2);
    float inv0 = 1.0f / lsum0, inv1 = 1.0f / lsum1;

    size_t gr = (size_t)(b*2048 + q0 + w*16 + (l >> 2));
#pragma unroll
    for (int nj = 0; nj < 8; ++nj) {
        int gc = h*64 + nj*8 + (l & 3)*2;
        *(u32*)(ctx + gr*512 + gc)     = pack_bf16(octx[nj][0]*inv0, octx[nj][1]*inv0);
        *(u32*)(ctx + (gr+8)*512 + gc) = pack_bf16(octx[nj][2]*inv1, octx[nj][3]*inv1);
    }
}

// ---- LayerNorm rows of 512 ----
__global__ __launch_bounds__(128)
void layernorm(const float* __restrict__ Y, const float* __restrict__ gamma,
               const float* __restrict__ beta, float* __restrict__ out)
{
    __shared__ float rs[4], rss[4];
    const int row = blockIdx.x, tid = threadIdx.x;
    const size_t off = (size_t)row*512 + tid*4;
    float4 val = *(const float4*)(Y + off);
    float s = val.x + val.y + val.z + val.w;
    float ss = val.x*val.x + val.y*val.y + val.z*val.z + val.w*val.w;
#pragma unroll
    for (int o = 16; o > 0; o >>= 1) { s += __shfl_xor_sync(0xffffffffu, s, o); ss += __shfl_xor_sync(0xffffffffu, ss, o); }
    int wid = tid >> 5;
    if ((tid & 31) == 0) { rs[wid] = s; rss[wid] = ss; }
    __syncthreads();
    s = rs[0]+rs[1]+rs[2]+rs[3]; ss = rss[0]+rss[1]+rss[2]+rss[3];
    float mean = s*(1.0f/512), var = ss*(1.0f/512) - mean*mean, rstd = rsqrtf(var + 1e-5f);
    float4 g = *(const float4*)(gamma + tid*4), be = *(const float4*)(beta + tid*4), o;
    o.x = (val.x-mean)*rstd*g.x + be.x; o.y = (val.y-mean)*rstd*g.y + be.y;
    o.z = (val.z-mean)*rstd*g.z + be.z; o.w = (val.w-mean)*rstd*g.w + be.w;
    *(float4*)(out + off) = o;
}

extern "C" void kernel_launch(void* const* d_in, const int* in_sizes, int n_in,
                              void* d_out, int out_size)
{
    const float* Qd = (const float*)d_in[0];  const float* Qt = (const float*)d_in[1];
    const float* Kd = (const float*)d_in[2];  const float* Kt = (const float*)d_in[3];
    const float* Vd = (const float*)d_in[4];  const float* Vt = (const float*)d_in[5];
    const float* bqd = (const float*)d_in[7];
    const float* bqt = (const float*)d_in[9];
    const float* bkd = (const float*)d_in[11];
    const float* bkt = (const float*)d_in[13];
    const float* bvd = (const float*)d_in[15];
    const float* bvt = (const float*)d_in[17];
    const float* bo  = (const float*)d_in[19];
    const float* gamma = (const float*)d_in[20]; const float* beta = (const float*)d_in[21];
    float* out = (float*)d_out;

    __nv_bfloat16 *wt, *qdb, *qtb, *kdb, *ktb, *vbp, *ctxb; float* y;
    cudaGetSymbolAddress((void**)&wt,  g_wt);
    cudaGetSymbolAddress((void**)&qdb, g_qdb);
    cudaGetSymbolAddress((void**)&qtb, g_qtb);
    cudaGetSymbolAddress((void**)&kdb, g_kdb);
    cudaGetSymbolAddress((void**)&ktb, g_ktb);
    cudaGetSymbolAddress((void**)&vbp, g_vb);
    cudaGetSymbolAddress((void**)&ctxb, g_ctx);
    cudaGetSymbolAddress((void**)&y,   g_y);

    cudaFuncSetAttribute(mma_attn, cudaFuncAttributeMaxDynamicSharedMemorySize, ATT_SMEM);

    wtrans<<<dim3(16,16,7), dim3(32,8)>>>((const float*)d_in[6], (const float*)d_in[8],
        (const float*)d_in[10], (const float*)d_in[12], (const float*)d_in[14],
        (const float*)d_in[16], (const float*)d_in[18], wt);

    size_t W = (size_t)512*512;

    GArgs p{};
    p.X0[0]=Qd; p.X0[1]=Qt; p.X0[2]=Kd; p.X0[3]=Kt;
    p.W0[0]=wt; p.W0[1]=wt+W; p.W0[2]=wt+2*W; p.W0[3]=wt+3*W;
    p.b0[0]=bqd; p.b0[1]=bqt; p.b0[2]=bkd; p.b0[3]=bkt;
    p.Y[0]=qdb; p.Y[1]=qtb; p.Y[2]=kdb; p.Y[3]=ktb;
    mma_gemm<true,false,false><<<dim3(4,64,4),256>>>(p);

    GArgs v{};
    v.X0[0]=Vd; v.W0[0]=wt+4*W; v.b0[0]=bvd; v.Y[0]=vbp;
    v.X1=Vt; v.W1=wt+5*W; v.b1=bvt;
    mma_gemm<true,true,false><<<dim3(4,64,1),256>>>(v);

    mma_attn<<<dim3(16,32),256,ATT_SMEM>>>(qdb, qtb, kdb, ktb, vbp, ctxb);

    GArgs o{};
    o.X0[0]=ctxb; o.W0[0]=wt+6*W; o.b0[0]=bo; o.Y[0]=y; o.res=Qd;
    mma_gemm<false,false,true><<<dim3(4,64,1),256>>>(o);

    layernorm<<<8192,128>>>(y, gamma, beta, out);
}

// round 9
// speedup vs baseline: 8.2410x; 1.0413x over previous
#include <cuda_runtime.h>
#include <cuda_bf16.h>
typedef unsigned int u32; typedef unsigned long long u64;

__device__ __align__(16) __nv_bfloat16 g_wt[(size_t)7*512*512];
__device__ __align__(16) __nv_bfloat16 g_qdb[(size_t)8192*512];
__device__ __align__(16) __nv_bfloat16 g_qtb[(size_t)8192*512];
__device__ __align__(16) __nv_bfloat16 g_kdb[(size_t)8192*512];
__device__ __align__(16) __nv_bfloat16 g_ktb[(size_t)8192*512];
__device__ __align__(16) __nv_bfloat16 g_vb [(size_t)8192*512];
__device__ __align__(16) __nv_bfloat16 g_ctx[(size_t)8192*512];
__device__ __align__(16) float g_y[(size_t)8192*512];

__device__ __forceinline__ u32 smem_u32(const void* p) {
    u32 a; asm("{ .reg .u64 t; cvta.to.shared.u64 t, %1; cvt.u32.u64 %0, t; }" : "=r"(a) : "l"(p)); return a;
}
__device__ __forceinline__ u32 pack_bf16(float lo, float hi) {
    u32 r; asm("cvt.rn.satfinite.bf16x2.f32 %0, %1, %2;" : "=r"(r) : "f"(hi), "f"(lo)); return r;
}
__device__ __forceinline__ float ex2f(float x) {
    float y; asm("ex2.approx.f32 %0, %1;" : "=f"(y) : "f"(x)); return y;
}
__device__ __forceinline__ void ldsm4(u32* r, u32 a) {
    asm volatile("ldmatrix.sync.aligned.m8n8.x4.shared.b16 {%0,%1,%2,%3}, [%4];"
        : "=r"(r[0]), "=r"(r[1]), "=r"(r[2]), "=r"(r[3]) : "r"(a));
}
__device__ __forceinline__ void ldsm4t(u32* r, u32 a) {
    asm volatile("ldmatrix.sync.aligned.m8n8.x4.trans.shared.b16 {%0,%1,%2,%3}, [%4];"
        : "=r"(r[0]), "=r"(r[1]), "=r"(r[2]), "=r"(r[3]) : "r"(a));
}
__device__ __forceinline__ void mma16(float* c, const u32* a, u32 b0, u32 b1) {
    asm volatile("mma.sync.aligned.m16n8k16.row.col.f32.bf16.bf16.f32 "
        "{%0,%1,%2,%3}, {%4,%5,%6,%7}, {%8,%9}, {%0,%1,%2,%3};"
        : "+f"(c[0]), "+f"(c[1]), "+f"(c[2]), "+f"(c[3])
        : "r"(a[0]), "r"(a[1]), "r"(a[2]), "r"(a[3]), "r"(b0), "r"(b1));
}
__device__ __forceinline__ void cpa16(u32 dst, const void* src) {
    asm volatile("cp.async.cg.shared.global [%0], [%1], 16;" :: "r"(dst), "l"(src));
}
#define CP_COMMIT() asm volatile("cp.async.commit_group;" ::: "memory")
#define CP_WAIT(n)  asm volatile("cp.async.wait_group %0;" :: "n"(n) : "memory")

// ---- weight transpose + bf16: Wt[n][k] = W[k][n], 7 matrices ----
__global__ void wtrans(const float* w0, const float* w1, const float* w2, const float* w3,
                       const float* w4, const float* w5, const float* w6, __nv_bfloat16* dst)
{
    __shared__ float t[32][33];
    const float* W;
    switch (blockIdx.z) { case 0: W=w0; break; case 1: W=w1; break; case 2: W=w2; break;
        case 3: W=w3; break; case 4: W=w4; break; case 5: W=w5; break; default: W=w6; }
    int bx = blockIdx.x*32, by = blockIdx.y*32, tx = threadIdx.x, ty = threadIdx.y;
#pragma unroll
    for (int i = 0; i < 4; ++i) t[ty*4+i][tx] = W[(size_t)(by+ty*4+i)*512 + bx+tx];
    __syncthreads();
    __nv_bfloat16* D = dst + (size_t)blockIdx.z*512*512;
#pragma unroll
    for (int i = 0; i < 4; ++i) D[(size_t)(bx+ty*4+i)*512 + by+tx] = __float2bfloat16(t[tx][ty*4+i]);
}

struct GArgs {
    const void* X0[5]; const __nv_bfloat16* W0[5];
    const float* b0[5]; void* Y[5]; float scale[5];
    const void* X1; const __nv_bfloat16* W1; const float* b1;
    const float* res;
};

// ---- HMMA GEMM, register-prefetch pipelined. 128x128 tile, 8 warps 2x4 ----
// z==4 runs the dual (V) GEMM: K=1024 over X0[4]/W0[4] then X1/W1, bias b0[4]+b1.
template<bool AFP32, bool OUTF32>
__global__ __launch_bounds__(256, 2)
void mma_gemm(GArgs a)
{
    __shared__ __align__(16) __nv_bfloat16 As[128*72];
    __shared__ __align__(16) __nv_bfloat16 Bs[128*72];
    const int tid = threadIdx.x, l = tid & 31, w = tid >> 5, wr = w >> 2, wc = w & 3;
    const int m0 = blockIdx.y*128, n0 = blockIdx.x*128, z = blockIdx.z;
    const u32 sA = smem_u32(As), sB = smem_u32(Bs);
    const void* X0 = a.X0[z]; const __nv_bfloat16* W0 = a.W0[z];
    const float* b0p = a.b0[z]; void* Yout = a.Y[z];
    const float scl = a.scale[z];
    const bool dual = (z == 4);
    const int NCH = dual ? 16 : 8;

    float acc[4][4][4];
#pragma unroll
    for (int i = 0; i < 4; ++i)
#pragma unroll
        for (int j = 0; j < 4; ++j)
#pragma unroll
            for (int q = 0; q < 4; ++q) acc[i][j][q] = 0.0f;

    uint2 aR[8]; uint4 bR[4];
    auto loadc = [&](int c) {
        const void* X = (dual && c >= 8) ? a.X1 : X0;
        const __nv_bfloat16* W = (dual && c >= 8) ? a.W1 : W0;
        const int k0 = (c & 7) * 64;
        if (AFP32) {
            const float* Xf = (const float*)X;
#pragma unroll
            for (int i = 0; i < 8; ++i) {
                int v = i*256 + tid, row = v >> 4, c4 = v & 15;
                float4 x = *(const float4*)(Xf + (size_t)(m0+row)*512 + k0 + c4*4);
                aR[i] = make_uint2(pack_bf16(x.x,x.y), pack_bf16(x.z,x.w));
            }
        } else {
            const __nv_bfloat16* Xb = (const __nv_bfloat16*)X;
#pragma unroll
            for (int i = 0; i < 4; ++i) {
                int v = i*256 + tid, row = v >> 3, c8 = v & 7;
                uint4 x = *(const uint4*)(Xb + (size_t)(m0+row)*512 + k0 + c8*8);
                aR[2*i]   = make_uint2(x.x, x.y);
                aR[2*i+1] = make_uint2(x.z, x.w);
            }
        }
#pragma unroll
        for (int i = 0; i < 4; ++i) {
            int v = i*256 + tid, row = v >> 3, c8 = v & 7;
            bR[i] = *(const uint4*)(W + (size_t)(n0+row)*512 + k0 + c8*8);
        }
    };

    loadc(0);
#pragma unroll 1
    for (int c = 0; c < NCH; ++c) {
        __syncthreads();
        if (AFP32) {
#pragma unroll
            for (int i = 0; i < 8; ++i) {
                int v = i*256 + tid, row = v >> 4, c4 = v & 15;
                *(uint2*)(As + row*72 + c4*4) = aR[i];
            }
        } else {
#pragma unroll
            for (int i = 0; i < 4; ++i) {
                int v = i*256 + tid, row = v >> 3, c8 = v & 7;
                *(uint4*)(As + row*72 + c8*8) = make_uint4(aR[2*i].x, aR[2*i].y, aR[2*i+1].x, aR[2*i+1].y);
            }
        }
#pragma unroll
        for (int i = 0; i < 4; ++i) {
            int v = i*256 + tid, row = v >> 3, c8 = v & 7;
            *(uint4*)(Bs + row*72 + c8*8) = bR[i];
        }
        __syncthreads();
        if (c + 1 < NCH) loadc(c + 1);
#pragma unroll
        for (int ks = 0; ks < 4; ++ks) {
            u32 af[4][4];
#pragma unroll
            for (int mi = 0; mi < 4; ++mi)
                ldsm4(af[mi], sA + ((wr*64 + mi*16 + (l & 15))*72 + ks*16 + (l >> 4)*8)*2);
#pragma unroll
            for (int ni = 0; ni < 2; ++ni) {
                u32 bf[4];
                ldsm4(bf, sB + ((wc*32 + ni*16 + (l & 15))*72 + ks*16 + (l >> 4)*8)*2);
#pragma unroll
                for (int mi = 0; mi < 4; ++mi) {
                    mma16(acc[mi][ni*2],   af[mi], bf[0], bf[2]);
                    mma16(acc[mi][ni*2+1], af[mi], bf[1], bf[3]);
                }
            }
        }
    }
#pragma unroll
    for (int mi = 0; mi < 4; ++mi)
#pragma unroll
        for (int nj = 0; nj < 4; ++nj) {
            int gr = m0 + wr*64 + mi*16 + (l >> 2);
            int gc = n0 + wc*32 + nj*8 + (l & 3)*2;
            float2 bv = *(const float2*)(b0p + gc);
            if (dual) { float2 b2 = *(const float2*)(a.b1 + gc); bv.x += b2.x; bv.y += b2.y; }
            float* cc = acc[mi][nj];
            if (OUTF32) {
                float* Y = (float*)Yout;
                float2 r0 = *(const float2*)(a.res + (size_t)gr*512 + gc);
                float2 r1 = *(const float2*)(a.res + (size_t)(gr+8)*512 + gc);
                *(float2*)(Y + (size_t)gr*512 + gc)     = make_float2(cc[0]+bv.x+r0.x, cc[1]+bv.y+r0.y);
                *(float2*)(Y + (size_t)(gr+8)*512 + gc) = make_float2(cc[2]+bv.x+r1.x, cc[3]+bv.y+r1.y);
            } else {
                __nv_bfloat16* Y = (__nv_bfloat16*)Yout;
                *(u32*)(Y + (size_t)gr*512 + gc)     = pack_bf16((cc[0]+bv.x)*scl, (cc[1]+bv.y)*scl);
                *(u32*)(Y + (size_t)(gr+8)*512 + gc) = pack_bf16((cc[2]+bv.x)*scl, (cc[3]+bv.y)*scl);
            }
        }
}

// ---- HMMA flash attention: 4 warps x 32 q-rows, 128-key tiles, cp.async DB ----
// smem: K0 @0 [128][136], K1 @34816, V0 @69632 [128][72], V1 @88064 ; total 106496
#define ATT_SMEM 106496
__global__ __launch_bounds__(128, 2)
void mma_attn(const __nv_bfloat16* __restrict__ qd, const __nv_bfloat16* __restrict__ qt,
              const __nv_bfloat16* __restrict__ kd, const __nv_bfloat16* __restrict__ kt,
              const __nv_bfloat16* __restrict__ vb, __nv_bfloat16* __restrict__ ctx)
{
    extern __shared__ __align__(16) char sm[];
    const u32 smb = smem_u32(sm);
    const int tid = threadIdx.x, l = tid & 31, w = tid >> 5;
    const int q0 = blockIdx.x*128, bh = blockIdx.y, b = bh >> 3, h = bh & 7;
    const size_t rbase = (size_t)b*2048*512 + h*64;

    // prologue: Q tile [128][128]=qd||qt into K-buf0, then frags (32 rows/warp) to regs
#pragma unroll
    for (int i = 0; i < 16; ++i) {
        int v = i*128 + tid, row = v >> 4, c16 = v & 15;
        const __nv_bfloat16* src = (c16 < 8) ? qd : qt;
        uint4 x = *(const uint4*)(src + rbase + (size_t)(q0+row)*512 + (c16 & 7)*8);
        *(uint4*)(sm + (row*136 + c16*8)*2) = x;
    }
    __syncthreads();
    u32 qf[8][2][4];
#pragma unroll
    for (int ks = 0; ks < 8; ++ks)
#pragma unroll
        for (int mb = 0; mb < 2; ++mb)
            ldsm4(qf[ks][mb], smb + ((w*32 + mb*16 + (l & 15))*136 + ks*16 + (l >> 4)*8)*2);
    __syncthreads();

    auto issue = [&](int kti, int buf) {
        const int k0 = kti*128;
        const u32 dK = smb + buf*34816, dV = smb + 69632 + buf*18432;
#pragma unroll
        for (int i = 0; i < 16; ++i) {
            int v = i*128 + tid, row = v >> 4, c16 = v & 15;
            const __nv_bfloat16* src = (c16 < 8) ? kd : kt;
            cpa16(dK + (row*136 + c16*8)*2, src + rbase + (size_t)(k0+row)*512 + (c16 & 7)*8);
        }
#pragma unroll
        for (int i = 0; i < 8; ++i) {   // V tile: 128 rows (fixed: was 4 iters -> half tile)
            int v = i*128 + tid, row = v >> 3, c8 = v & 7;
            cpa16(dV + (row*72 + c8*8)*2, vb + rbase + (size_t)(k0+row)*512 + c8*8);
        }
    };

    float octx[2][8][4];
#pragma unroll
    for (int mb = 0; mb < 2; ++mb)
#pragma unroll
        for (int i = 0; i < 8; ++i)
#pragma unroll
            for (int q = 0; q < 4; ++q) octx[mb][i][q] = 0.0f;
    float ls[2][2] = {{0.f,0.f},{0.f,0.f}};

    issue(0, 0); CP_COMMIT();
#pragma unroll 1
    for (int kti = 0; kti < 16; ++kti) {
        if (kti < 15) { issue(kti+1, (kti+1)&1); CP_COMMIT(); CP_WAIT(1); }
        else CP_WAIT(0);
        __syncthreads();
        const u32 sK = smb + (kti&1)*34816, sV = smb + 69632 + (kti&1)*18432;

#pragma unroll
        for (int qtr = 0; qtr < 4; ++qtr) {   // 32-key quarters
            float c[2][4][4];
#pragma unroll
            for (int mb = 0; mb < 2; ++mb)
#pragma unroll
                for (int i = 0; i < 4; ++i)
#pragma unroll
                    for (int q = 0; q < 4; ++q) c[mb][i][q] = 0.0f;
#pragma unroll
            for (int ks = 0; ks < 8; ++ks)
#pragma unroll
                for (int kb = 0; kb < 2; ++kb) {
                    u32 bf[4];
                    ldsm4(bf, sK + ((qtr*32 + kb*16 + (l & 15))*136 + ks*16 + (l >> 4)*8)*2);
#pragma unroll
                    for (int mb = 0; mb < 2; ++mb) {
                        mma16(c[mb][kb*2],   qf[ks][mb], bf[0], bf[2]);
                        mma16(c[mb][kb*2+1], qf[ks][mb], bf[1], bf[3]);
                    }
                }
            // softmax: exp2 (scale pre-folded into Q), P as A-frags
            u32 pa[2][2][4];
#pragma unroll
            for (int mb = 0; mb < 2; ++mb)
#pragma unroll
                for (int kb = 0; kb < 2; ++kb) {
                    float p0 = ex2f(c[mb][kb*2][0]),   p1 = ex2f(c[mb][kb*2][1]);
                    float p2 = ex2f(c[mb][kb*2][2]),   p3 = ex2f(c[mb][kb*2][3]);
                    float p4 = ex2f(c[mb][kb*2+1][0]), p5 = ex2f(c[mb][kb*2+1][1]);
                    float p6 = ex2f(c[mb][kb*2+1][2]), p7 = ex2f(c[mb][kb*2+1][3]);
                    ls[mb][0] += p0 + p1 + p4 + p5;
                    ls[mb][1] += p2 + p3 + p6 + p7;
                    pa[mb][kb][0] = pack_bf16(p0,p1); pa[mb][kb][1] = pack_bf16(p2,p3);
                    pa[mb][kb][2] = pack_bf16(p4,p5); pa[mb][kb][3] = pack_bf16(p6,p7);
                }
#pragma unroll
            for (int kb = 0; kb < 2; ++kb)
#pragma unroll
                for (int nj4 = 0; nj4 < 4; ++nj4) {
                    u32 bf[4];
                    ldsm4t(bf, sV + ((qtr*32 + kb*16 + (l & 15))*72 + nj4*16 + (l >> 4)*8)*2);
#pragma unroll
                    for (int mb = 0; mb < 2; ++mb) {
                        mma16(octx[mb][2*nj4],   pa[mb][kb], bf[0], bf[1]);
                        mma16(octx[mb][2*nj4+1], pa[mb][kb], bf[2], bf[3]);
                    }
                }
        }
        __syncthreads();
    }
#pragma unroll
    for (int mb = 0; mb < 2; ++mb) {
        ls[mb][0] += __shfl_xor_sync(0xffffffffu, ls[mb][0], 1);
        ls[mb][0] += __shfl_xor_sync(0xffffffffu, ls[mb][0], 2);
        ls[mb][1] += __shfl_xor_sync(0xffffffffu, ls[mb][1], 1);
        ls[mb][1] += __shfl_xor_sync(0xffffffffu, ls[mb][1], 2);
        float inv0 = 1.0f / ls[mb][0], inv1 = 1.0f / ls[mb][1];
        size_t gr = (size_t)(b*2048 + q0 + w*32 + mb*16 + (l >> 2));
#pragma unroll
        for (int nj = 0; nj < 8; ++nj) {
            int gc = h*64 + nj*8 + (l & 3)*2;
            *(u32*)(ctx + gr*512 + gc)     = pack_bf16(octx[mb][nj][0]*inv0, octx[mb][nj][1]*inv0);
            *(u32*)(ctx + (gr+8)*512 + gc) = pack_bf16(octx[mb][nj][2]*inv1, octx[mb][nj][3]*inv1);
        }
    }
}

// ---- LayerNorm rows of 512 ----
__global__ __launch_bounds__(128)
void layernorm(const float* __restrict__ Y, const float* __restrict__ gamma,
               const float* __restrict__ beta, float* __restrict__ out)
{
    __shared__ float rs[4], rss[4];
    const int row = blockIdx.x, tid = threadIdx.x;
    const size_t off = (size_t)row*512 + tid*4;
    float4 val = *(const float4*)(Y + off);
    float s = val.x + val.y + val.z + val.w;
    float ss = val.x*val.x + val.y*val.y + val.z*val.z + val.w*val.w;
#pragma unroll
    for (int o = 16; o > 0; o >>= 1) { s += __shfl_xor_sync(0xffffffffu, s, o); ss += __shfl_xor_sync(0xffffffffu, ss, o); }
    int wid = tid >> 5;
    if ((tid & 31) == 0) { rs[wid] = s; rss[wid] = ss; }
    __syncthreads();
    s = rs[0]+rs[1]+rs[2]+rs[3]; ss = rss[0]+rss[1]+rss[2]+rss[3];
    float mean = s*(1.0f/512), var = ss*(1.0f/512) - mean*mean, rstd = rsqrtf(var + 1e-5f);
    float4 g = *(const float4*)(gamma + tid*4), be = *(const float4*)(beta + tid*4), o;
    o.x = (val.x-mean)*rstd*g.x + be.x; o.y = (val.y-mean)*rstd*g.y + be.y;
    o.z = (val.z-mean)*rstd*g.z + be.z; o.w = (val.w-mean)*rstd*g.w + be.w;
    *(float4*)(out + off) = o;
}

extern "C" void kernel_launch(void* const* d_in, const int* in_sizes, int n_in,
                              void* d_out, int out_size)
{
    const float* Qd = (const float*)d_in[0];  const float* Qt = (const float*)d_in[1];
    const float* Kd = (const float*)d_in[2];  const float* Kt = (const float*)d_in[3];
    const float* Vd = (const float*)d_in[4];  const float* Vt = (const float*)d_in[5];
    const float* bqd = (const float*)d_in[7];
    const float* bqt = (const float*)d_in[9];
    const float* bkd = (const float*)d_in[11];
    const float* bkt = (const float*)d_in[13];
    const float* bvd = (const float*)d_in[15];
    const float* bvt = (const float*)d_in[17];
    const float* bo  = (const float*)d_in[19];
    const float* gamma = (const float*)d_in[20]; const float* beta = (const float*)d_in[21];
    float* out = (float*)d_out;

    __nv_bfloat16 *wt, *qdb, *qtb, *kdb, *ktb, *vbp, *ctxb; float* y;
    cudaGetSymbolAddress((void**)&wt,  g_wt);
    cudaGetSymbolAddress((void**)&qdb, g_qdb);
    cudaGetSymbolAddress((void**)&qtb, g_qtb);
    cudaGetSymbolAddress((void**)&kdb, g_kdb);
    cudaGetSymbolAddress((void**)&ktb, g_ktb);
    cudaGetSymbolAddress((void**)&vbp, g_vb);
    cudaGetSymbolAddress((void**)&ctxb, g_ctx);
    cudaGetSymbolAddress((void**)&y,   g_y);

    cudaFuncSetAttribute(mma_attn, cudaFuncAttributeMaxDynamicSharedMemorySize, ATT_SMEM);

    wtrans<<<dim3(16,16,7), dim3(32,8)>>>((const float*)d_in[6], (const float*)d_in[8],
        (const float*)d_in[10], (const float*)d_in[12], (const float*)d_in[14],
        (const float*)d_in[16], (const float*)d_in[18], wt);

    size_t W = (size_t)512*512;
    const float QS = 0.18033688011112042f;   // 0.125 * log2(e)

    GArgs p{};
    p.X0[0]=Qd; p.X0[1]=Qt; p.X0[2]=Kd; p.X0[3]=Kt; p.X0[4]=Vd;
    p.W0[0]=wt; p.W0[1]=wt+W; p.W0[2]=wt+2*W; p.W0[3]=wt+3*W; p.W0[4]=wt+4*W;
    p.b0[0]=bqd; p.b0[1]=bqt; p.b0[2]=bkd; p.b0[3]=bkt; p.b0[4]=bvd;
    p.Y[0]=qdb; p.Y[1]=qtb; p.Y[2]=kdb; p.Y[3]=ktb; p.Y[4]=vbp;
    p.scale[0]=QS; p.scale[1]=QS; p.scale[2]=1.f; p.scale[3]=1.f; p.scale[4]=1.f;
    p.X1=Vt; p.W1=wt+5*W; p.b1=bvt;
    mma_gemm<true,false><<<dim3(4,64,5),256>>>(p);

    mma_attn<<<dim3(16,32),128,ATT_SMEM>>>(qdb, qtb, kdb, ktb, vbp, ctxb);

    GArgs o{};
    o.X0[0]=ctxb; o.W0[0]=wt+6*W; o.b0[0]=bo; o.Y[0]=y; o.scale[0]=1.f; o.res=Qd;
    mma_gemm<false,true><<<dim3(4,64,1),256>>>(o);

    layernorm<<<8192,128>>>(y, gamma, beta, out);
}

// round 10
// speedup vs baseline: 8.6399x; 1.0484x over previous
#include <cuda_runtime.h>
#include <cuda_bf16.h>
typedef unsigned int u32; typedef unsigned long long u64;

__device__ __align__(16) __nv_bfloat16 g_wt[(size_t)7*512*512];
__device__ __align__(16) __nv_bfloat16 g_qdb[(size_t)8192*512];
__device__ __align__(16) __nv_bfloat16 g_qtb[(size_t)8192*512];
__device__ __align__(16) __nv_bfloat16 g_kdb[(size_t)8192*512];
__device__ __align__(16) __nv_bfloat16 g_ktb[(size_t)8192*512];
__device__ __align__(16) __nv_bfloat16 g_vb [(size_t)8192*512];
__device__ __align__(16) __nv_bfloat16 g_ctx[(size_t)8192*512];
__device__ __align__(16) float g_y[(size_t)8192*512];

__device__ __forceinline__ u32 smem_u32(const void* p) {
    u32 a; asm("{ .reg .u64 t; cvta.to.shared.u64 t, %1; cvt.u32.u64 %0, t; }" : "=r"(a) : "l"(p)); return a;
}
__device__ __forceinline__ u32 pack_bf16(float lo, float hi) {
    u32 r; asm("cvt.rn.satfinite.bf16x2.f32 %0, %1, %2;" : "=r"(r) : "f"(hi), "f"(lo)); return r;
}
__device__ __forceinline__ float ex2f(float x) {
    float y; asm("ex2.approx.f32 %0, %1;" : "=f"(y) : "f"(x)); return y;
}
__device__ __forceinline__ void ldsm4(u32* r, u32 a) {
    asm volatile("ldmatrix.sync.aligned.m8n8.x4.shared.b16 {%0,%1,%2,%3}, [%4];"
        : "=r"(r[0]), "=r"(r[1]), "=r"(r[2]), "=r"(r[3]) : "r"(a));
}
__device__ __forceinline__ void ldsm4t(u32* r, u32 a) {
    asm volatile("ldmatrix.sync.aligned.m8n8.x4.trans.shared.b16 {%0,%1,%2,%3}, [%4];"
        : "=r"(r[0]), "=r"(r[1]), "=r"(r[2]), "=r"(r[3]) : "r"(a));
}
__device__ __forceinline__ void mma16(float* c, const u32* a, u32 b0, u32 b1) {
    asm volatile("mma.sync.aligned.m16n8k16.row.col.f32.bf16.bf16.f32 "
        "{%0,%1,%2,%3}, {%4,%5,%6,%7}, {%8,%9}, {%0,%1,%2,%3};"
        : "+f"(c[0]), "+f"(c[1]), "+f"(c[2]), "+f"(c[3])
        : "r"(a[0]), "r"(a[1]), "r"(a[2]), "r"(a[3]), "r"(b0), "r"(b1));
}
__device__ __forceinline__ void cpa16(u32 dst, const void* src) {
    asm volatile("cp.async.cg.shared.global [%0], [%1], 16;" :: "r"(dst), "l"(src));
}
#define CP_COMMIT() asm volatile("cp.async.commit_group;" ::: "memory")
#define CP_WAIT(n)  asm volatile("cp.async.wait_group %0;" :: "n"(n) : "memory")

// ---- weight transpose + bf16: Wt[n][k] = W[k][n], 7 matrices ----
__global__ void wtrans(const float* w0, const float* w1, const float* w2, const float* w3,
                       const float* w4, const float* w5, const float* w6, __nv_bfloat16* dst)
{
    __shared__ float t[32][33];
    const float* W;
    switch (blockIdx.z) { case 0: W=w0; break; case 1: W=w1; break; case 2: W=w2; break;
        case 3: W=w3; break; case 4: W=w4; break; case 5: W=w5; break; default: W=w6; }
    int bx = blockIdx.x*32, by = blockIdx.y*32, tx = threadIdx.x, ty = threadIdx.y;
#pragma unroll
    for (int i = 0; i < 4; ++i) t[ty*4+i][tx] = W[(size_t)(by+ty*4+i)*512 + bx+tx];
    __syncthreads();
    __nv_bfloat16* D = dst + (size_t)blockIdx.z*512*512;
#pragma unroll
    for (int i = 0; i < 4; ++i) D[(size_t)(bx+ty*4+i)*512 + by+tx] = __float2bfloat16(t[tx][ty*4+i]);
}

struct GArgs {
    const void* X0[5]; const __nv_bfloat16* W0[5];
    const float* b0[5]; void* Y[5]; float scale[5];
    const void* X1; const __nv_bfloat16* W1; const float* b1;
    const float* res;
};

// ---- HMMA GEMM: double-buffered smem, cp.async weights, reg-prefetch A ----
// smem layout per buffer (36864 B): A [128][72] bf16 @0, B [128][72] bf16 @18432
#define GEMM_SMEM 73728
template<bool AFP32, bool OUTF32>
__global__ __launch_bounds__(256, 2)
void mma_gemm(GArgs a)
{
    extern __shared__ __align__(16) char gsm[];
    const u32 smb = smem_u32(gsm);
    const int tid = threadIdx.x, l = tid & 31, w = tid >> 5, wr = w >> 2, wc = w & 3;
    const int m0 = blockIdx.y*128, n0 = blockIdx.x*128, z = blockIdx.z;
    const void* X0 = a.X0[z]; const __nv_bfloat16* W0 = a.W0[z];
    const float* b0p = a.b0[z]; void* Yout = a.Y[z];
    const float scl = a.scale[z];
    const bool dual = (z == 4);
    const int NCH = dual ? 16 : 8;

    float acc[4][4][4];
#pragma unroll
    for (int i = 0; i < 4; ++i)
#pragma unroll
        for (int j = 0; j < 4; ++j)
#pragma unroll
            for (int q = 0; q < 4; ++q) acc[i][j][q] = 0.0f;

    uint2 aR[8];
    auto ldA = [&](int c) {   // AFP32: LDG+convert to regs
        const float* Xf = (const float*)((dual && c >= 8) ? a.X1 : X0);
        const int k0 = (c & 7) * 64;
#pragma unroll
        for (int i = 0; i < 8; ++i) {
            int v = i*256 + tid, row = v >> 4, c4 = v & 15;
            float4 x = *(const float4*)(Xf + (size_t)(m0+row)*512 + k0 + c4*4);
            aR[i] = make_uint2(pack_bf16(x.x,x.y), pack_bf16(x.z,x.w));
        }
    };
    auto stsA = [&](int b) {
        __nv_bfloat16* As = (__nv_bfloat16*)(gsm + b*36864);
#pragma unroll
        for (int i = 0; i < 8; ++i) {
            int v = i*256 + tid, row = v >> 4, c4 = v & 15;
            *(uint2*)(As + row*72 + c4*4) = aR[i];
        }
    };
    auto cpA = [&](int c, int b) {   // bf16 A path
        const __nv_bfloat16* Xb = (const __nv_bfloat16*)X0;
        const u32 dA = smb + b*36864;
        const int k0 = (c & 7) * 64;
#pragma unroll
        for (int i = 0; i < 4; ++i) {
            int v = i*256 + tid, row = v >> 3, c8 = v & 7;
            cpa16(dA + (row*72 + c8*8)*2, Xb + (size_t)(m0+row)*512 + k0 + c8*8);
        }
    };
    auto cpB = [&](int c, int b) {
        const __nv_bfloat16* W = (dual && c >= 8) ? a.W1 : W0;
        const u32 dB = smb + b*36864 + 18432;
        const int k0 = (c & 7) * 64;
#pragma unroll
        for (int i = 0; i < 4; ++i) {
            int v = i*256 + tid, row = v >> 3, c8 = v & 7;
            cpa16(dB + (row*72 + c8*8)*2, W + (size_t)(n0+row)*512 + k0 + c8*8);
        }
    };

    // prologue: chunk 0 into buffer 0
    if (AFP32) { ldA(0); stsA(0); } else cpA(0, 0);
    cpB(0, 0); CP_COMMIT();

#pragma unroll 1
    for (int c = 0; c < NCH; ++c) {
        const int buf = c & 1;
        if (c + 1 < NCH) {
            if (AFP32) ldA(c + 1);          // LDGs in flight during MMA below
            else cpA(c + 1, buf ^ 1);
            cpB(c + 1, buf ^ 1);
            CP_COMMIT(); CP_WAIT(1);
        } else CP_WAIT(0);
        __syncthreads();                    // buf(c) data (cp.async + STS) visible

        const u32 sA = smb + buf*36864, sB = sA + 18432;
#pragma unroll
        for (int ks = 0; ks < 4; ++ks) {
            u32 af[4][4];
#pragma unroll
            for (int mi = 0; mi < 4; ++mi)
                ldsm4(af[mi], sA + ((wr*64 + mi*16 + (l & 15))*72 + ks*16 + (l >> 4)*8)*2);
#pragma unroll
            for (int ni = 0; ni < 2; ++ni) {
                u32 bf[4];
                ldsm4(bf, sB + ((wc*32 + ni*16 + (l & 15))*72 + ks*16 + (l >> 4)*8)*2);
#pragma unroll
                for (int mi = 0; mi < 4; ++mi) {
                    mma16(acc[mi][ni*2],   af[mi], bf[0], bf[2]);
                    mma16(acc[mi][ni*2+1], af[mi], bf[1], bf[3]);
                }
            }
        }
        if (AFP32 && c + 1 < NCH) stsA(buf ^ 1);   // regs ready; idle buffer
        __syncthreads();                    // buf(c) reads done -> next writes safe
    }
#pragma unroll
    for (int mi = 0; mi < 4; ++mi)
#pragma unroll
        for (int nj = 0; nj < 4; ++nj) {
            int gr = m0 + wr*64 + mi*16 + (l >> 2);
            int gc = n0 + wc*32 + nj*8 + (l & 3)*2;
            float2 bv = *(const float2*)(b0p + gc);
            if (dual) { float2 b2 = *(const float2*)(a.b1 + gc); bv.x += b2.x; bv.y += b2.y; }
            float* cc = acc[mi][nj];
            if (OUTF32) {
                float* Y = (float*)Yout;
                float2 r0 = *(const float2*)(a.res + (size_t)gr*512 + gc);
                float2 r1 = *(const float2*)(a.res + (size_t)(gr+8)*512 + gc);
                *(float2*)(Y + (size_t)gr*512 + gc)     = make_float2(cc[0]+bv.x+r0.x, cc[1]+bv.y+r0.y);
                *(float2*)(Y + (size_t)(gr+8)*512 + gc) = make_float2(cc[2]+bv.x+r1.x, cc[3]+bv.y+r1.y);
            } else {
                __nv_bfloat16* Y = (__nv_bfloat16*)Yout;
                *(u32*)(Y + (size_t)gr*512 + gc)     = pack_bf16((cc[0]+bv.x)*scl, (cc[1]+bv.y)*scl);
                *(u32*)(Y + (size_t)(gr+8)*512 + gc) = pack_bf16((cc[2]+bv.x)*scl, (cc[3]+bv.y)*scl);
            }
        }
}

// ---- HMMA flash attention: 4 warps x 32 q-rows, 128-key tiles, cp.async DB ----
// smem: K0 @0 [128][136], K1 @34816, V0 @69632 [128][72], V1 @88064 ; total 106496
#define ATT_SMEM 106496
__global__ __launch_bounds__(128, 2)
void mma_attn(const __nv_bfloat16* __restrict__ qd, const __nv_bfloat16* __restrict__ qt,
              const __nv_bfloat16* __restrict__ kd, const __nv_bfloat16* __restrict__ kt,
              const __nv_bfloat16* __restrict__ vb, __nv_bfloat16* __restrict__ ctx)
{
    extern __shared__ __align__(16) char sm[];
    const u32 smb = smem_u32(sm);
    const int tid = threadIdx.x, l = tid & 31, w = tid >> 5;
    const int q0 = blockIdx.x*128, bh = blockIdx.y, b = bh >> 3, h = bh & 7;
    const size_t rbase = (size_t)b*2048*512 + h*64;

#pragma unroll
    for (int i = 0; i < 16; ++i) {
        int v = i*128 + tid, row = v >> 4, c16 = v & 15;
        const __nv_bfloat16* src = (c16 < 8) ? qd : qt;
        uint4 x = *(const uint4*)(src + rbase + (size_t)(q0+row)*512 + (c16 & 7)*8);
        *(uint4*)(sm + (row*136 + c16*8)*2) = x;
    }
    __syncthreads();
    u32 qf[8][2][4];
#pragma unroll
    for (int ks = 0; ks < 8; ++ks)
#pragma unroll
        for (int mb = 0; mb < 2; ++mb)
            ldsm4(qf[ks][mb], smb + ((w*32 + mb*16 + (l & 15))*136 + ks*16 + (l >> 4)*8)*2);
    __syncthreads();

    auto issue = [&](int kti, int buf) {
        const int k0 = kti*128;
        const u32 dK = smb + buf*34816, dV = smb + 69632 + buf*18432;
#pragma unroll
        for (int i = 0; i < 16; ++i) {
            int v = i*128 + tid, row = v >> 4, c16 = v & 15;
            const __nv_bfloat16* src = (c16 < 8) ? kd : kt;
            cpa16(dK + (row*136 + c16*8)*2, src + rbase + (size_t)(k0+row)*512 + (c16 & 7)*8);
        }
#pragma unroll
        for (int i = 0; i < 8; ++i) {
            int v = i*128 + tid, row = v >> 3, c8 = v & 7;
            cpa16(dV + (row*72 + c8*8)*2, vb + rbase + (size_t)(k0+row)*512 + c8*8);
        }
    };

    float octx[2][8][4];
#pragma unroll
    for (int mb = 0; mb < 2; ++mb)
#pragma unroll
        for (int i = 0; i < 8; ++i)
#pragma unroll
            for (int q = 0; q < 4; ++q) octx[mb][i][q] = 0.0f;
    float ls[2][2] = {{0.f,0.f},{0.f,0.f}};

    issue(0, 0); CP_COMMIT();
#pragma unroll 1
    for (int kti = 0; kti < 16; ++kti) {
        if (kti < 15) { issue(kti+1, (kti+1)&1); CP_COMMIT(); CP_WAIT(1); }
        else CP_WAIT(0);
        __syncthreads();
        const u32 sK = smb + (kti&1)*34816, sV = smb + 69632 + (kti&1)*18432;

#pragma unroll
        for (int qtr = 0; qtr < 4; ++qtr) {
            float c[2][4][4];
#pragma unroll
            for (int mb = 0; mb < 2; ++mb)
#pragma unroll
                for (int i = 0; i < 4; ++i)
#pragma unroll
                    for (int q = 0; q < 4; ++q) c[mb][i][q] = 0.0f;
#pragma unroll
            for (int ks = 0; ks < 8; ++ks)
#pragma unroll
                for (int kb = 0; kb < 2; ++kb) {
                    u32 bf[4];
                    ldsm4(bf, sK + ((qtr*32 + kb*16 + (l & 15))*136 + ks*16 + (l >> 4)*8)*2);
#pragma unroll
                    for (int mb = 0; mb < 2; ++mb) {
                        mma16(c[mb][kb*2],   qf[ks][mb], bf[0], bf[2]);
                        mma16(c[mb][kb*2+1], qf[ks][mb], bf[1], bf[3]);
                    }
                }
            u32 pa[2][2][4];
#pragma unroll
            for (int mb = 0; mb < 2; ++mb)
#pragma unroll
                for (int kb = 0; kb < 2; ++kb) {
                    float p0 = ex2f(c[mb][kb*2][0]),   p1 = ex2f(c[mb][kb*2][1]);
                    float p2 = ex2f(c[mb][kb*2][2]),   p3 = ex2f(c[mb][kb*2][3]);
                    float p4 = ex2f(c[mb][kb*2+1][0]), p5 = ex2f(c[mb][kb*2+1][1]);
                    float p6 = ex2f(c[mb][kb*2+1][2]), p7 = ex2f(c[mb][kb*2+1][3]);
                    ls[mb][0] += p0 + p1 + p4 + p5;
                    ls[mb][1] += p2 + p3 + p6 + p7;
                    pa[mb][kb][0] = pack_bf16(p0,p1); pa[mb][kb][1] = pack_bf16(p2,p3);
                    pa[mb][kb][2] = pack_bf16(p4,p5); pa[mb][kb][3] = pack_bf16(p6,p7);
                }
#pragma unroll
            for (int kb = 0; kb < 2; ++kb)
#pragma unroll
                for (int nj4 = 0; nj4 < 4; ++nj4) {
                    u32 bf[4];
                    ldsm4t(bf, sV + ((qtr*32 + kb*16 + (l & 15))*72 + nj4*16 + (l >> 4)*8)*2);
#pragma unroll
                    for (int mb = 0; mb < 2; ++mb) {
                        mma16(octx[mb][2*nj4],   pa[mb][kb], bf[0], bf[1]);
                        mma16(octx[mb][2*nj4+1], pa[mb][kb], bf[2], bf[3]);
                    }
                }
        }
        __syncthreads();
    }
#pragma unroll
    for (int mb = 0; mb < 2; ++mb) {
        ls[mb][0] += __shfl_xor_sync(0xffffffffu, ls[mb][0], 1);
        ls[mb][0] += __shfl_xor_sync(0xffffffffu, ls[mb][0], 2);
        ls[mb][1] += __shfl_xor_sync(0xffffffffu, ls[mb][1], 1);
        ls[mb][1] += __shfl_xor_sync(0xffffffffu, ls[mb][1], 2);
        float inv0 = 1.0f / ls[mb][0], inv1 = 1.0f / ls[mb][1];
        size_t gr = (size_t)(b*2048 + q0 + w*32 + mb*16 + (l >> 2));
#pragma unroll
        for (int nj = 0; nj < 8; ++nj) {
            int gc = h*64 + nj*8 + (l & 3)*2;
            *(u32*)(ctx + gr*512 + gc)     = pack_bf16(octx[mb][nj][0]*inv0, octx[mb][nj][1]*inv0);
            *(u32*)(ctx + (gr+8)*512 + gc) = pack_bf16(octx[mb][nj][2]*inv1, octx[mb][nj][3]*inv1);
        }
    }
}

// ---- LayerNorm rows of 512 ----
__global__ __launch_bounds__(128)
void layernorm(const float* __restrict__ Y, const float* __restrict__ gamma,
               const float* __restrict__ beta, float* __restrict__ out)
{
    __shared__ float rs[4], rss[4];
    const int row = blockIdx.x, tid = threadIdx.x;
    const size_t off = (size_t)row*512 + tid*4;
    float4 val = *(const float4*)(Y + off);
    float s = val.x + val.y + val.z + val.w;
    float ss = val.x*val.x + val.y*val.y + val.z*val.z + val.w*val.w;
#pragma unroll
    for (int o = 16; o > 0; o >>= 1) { s += __shfl_xor_sync(0xffffffffu, s, o); ss += __shfl_xor_sync(0xffffffffu, ss, o); }
    int wid = tid >> 5;
    if ((tid & 31) == 0) { rs[wid] = s; rss[wid] = ss; }
    __syncthreads();
    s = rs[0]+rs[1]+rs[2]+rs[3]; ss = rss[0]+rss[1]+rss[2]+rss[3];
    float mean = s*(1.0f/512), var = ss*(1.0f/512) - mean*mean, rstd = rsqrtf(var + 1e-5f);
    float4 g = *(const float4*)(gamma + tid*4), be = *(const float4*)(beta + tid*4), o;
    o.x = (val.x-mean)*rstd*g.x + be.x; o.y = (val.y-mean)*rstd*g.y + be.y;
    o.z = (val.z-mean)*rstd*g.z + be.z; o.w = (val.w-mean)*rstd*g.w + be.w;
    *(float4*)(out + off) = o;
}

extern "C" void kernel_launch(void* const* d_in, const int* in_sizes, int n_in,
                              void* d_out, int out_size)
{
    const float* Qd = (const float*)d_in[0];  const float* Qt = (const float*)d_in[1];
    const float* Kd = (const float*)d_in[2];  const float* Kt = (const float*)d_in[3];
    const float* Vd = (const float*)d_in[4];  const float* Vt = (const float*)d_in[5];
    const float* bqd = (const float*)d_in[7];
    const float* bqt = (const float*)d_in[9];
    const float* bkd = (const float*)d_in[11];
    const float* bkt = (const float*)d_in[13];
    const float* bvd = (const float*)d_in[15];
    const float* bvt = (const float*)d_in[17];
    const float* bo  = (const float*)d_in[19];
    const float* gamma = (const float*)d_in[20]; const float* beta = (const float*)d_in[21];
    float* out = (float*)d_out;

    __nv_bfloat16 *wt, *qdb, *qtb, *kdb, *ktb, *vbp, *ctxb; float* y;
    cudaGetSymbolAddress((void**)&wt,  g_wt);
    cudaGetSymbolAddress((void**)&qdb, g_qdb);
    cudaGetSymbolAddress((void**)&qtb, g_qtb);
    cudaGetSymbolAddress((void**)&kdb, g_kdb);
    cudaGetSymbolAddress((void**)&ktb, g_ktb);
    cudaGetSymbolAddress((void**)&vbp, g_vb);
    cudaGetSymbolAddress((void**)&ctxb, g_ctx);
    cudaGetSymbolAddress((void**)&y,   g_y);

    cudaFuncSetAttribute(mma_attn, cudaFuncAttributeMaxDynamicSharedMemorySize, ATT_SMEM);
    cudaFuncSetAttribute(mma_gemm<true,false>,  cudaFuncAttributeMaxDynamicSharedMemorySize, GEMM_SMEM);
    cudaFuncSetAttribute(mma_gemm<false,true>,  cudaFuncAttributeMaxDynamicSharedMemorySize, GEMM_SMEM);

    wtrans<<<dim3(16,16,7), dim3(32,8)>>>((const float*)d_in[6], (const float*)d_in[8],
        (const float*)d_in[10], (const float*)d_in[12], (const float*)d_in[14],
        (const float*)d_in[16], (const float*)d_in[18], wt);

    size_t W = (size_t)512*512;
    const float QS = 0.18033688011112042f;   // 0.125 * log2(e)

    GArgs p{};
    p.X0[0]=Qd; p.X0[1]=Qt; p.X0[2]=Kd; p.X0[3]=Kt; p.X0[4]=Vd;
    p.W0[0]=wt; p.W0[1]=wt+W; p.W0[2]=wt+2*W; p.W0[3]=wt+3*W; p.W0[4]=wt+4*W;
    p.b0[0]=bqd; p.b0[1]=bqt; p.b0[2]=bkd; p.b0[3]=bkt; p.b0[4]=bvd;
    p.Y[0]=qdb; p.Y[1]=qtb; p.Y[2]=kdb; p.Y[3]=ktb; p.Y[4]=vbp;
    p.scale[0]=QS; p.scale[1]=QS; p.scale[2]=1.f; p.scale[3]=1.f; p.scale[4]=1.f;
    p.X1=Vt; p.W1=wt+5*W; p.b1=bvt;
    mma_gemm<true,false><<<dim3(4,64,5),256,GEMM_SMEM>>>(p);

    mma_attn<<<dim3(16,32),128,ATT_SMEM>>>(qdb, qtb, kdb, ktb, vbp, ctxb);

    GArgs o{};
    o.X0[0]=ctxb; o.W0[0]=wt+6*W; o.b0[0]=bo; o.Y[0]=y; o.scale[0]=1.f; o.res=Qd;
    mma_gemm<false,true><<<dim3(4,64,1),256,GEMM_SMEM>>>(o);

    layernorm<<<8192,128>>>(y, gamma, beta, out);
}